// round 1
// baseline (speedup 1.0000x reference)
#include <cuda_runtime.h>

// Problem constants
#define CC   128          // channels
#define PCH  6            // polar channels
#define SS   131072       // spatial size per batch (32*64*64)
#define NB   2            // batch
#define NTOK (NB*SS)      // 262144 tokens
#define TOK  64           // tokens per CTA
#define PAD  129          // smem row stride (conflict-free both axes)
#define NTHREADS 256
#define NHEAD 8
#define HDIM  16

// ---- shared memory layout (float offsets) ----
#define OFF_A    0                       // residual1 / out1 buffer   [64][129]
#define OFF_B    (TOK*PAD)               // xn / attended / h / out2  [64][129]
#define OFF_Q    (2*TOK*PAD)             // Q  (also h1 chunk in FFN) [64][129]
#define OFF_K    (3*TOK*PAD)             // K                         [64][129]
#define OFF_V    (4*TOK*PAD)             // V                         [64][129]
#define OFF_WSH  (5*TOK*PAD)             // weight staging 32x128
#define OFF_WP   (OFF_WSH + 4096)        // Wp 6x128
#define OFF_BQ   (OFF_WP  + 768)
#define OFF_BK   (OFF_BQ  + 128)
#define OFF_BV   (OFF_BK  + 128)
#define OFF_BP   (OFF_BV  + 128)
#define OFF_BO   (OFF_BP  + 128)
#define OFF_G1   (OFF_BO  + 128)
#define OFF_BE1  (OFF_G1  + 128)
#define OFF_G2   (OFF_BE1 + 128)
#define OFF_BE2  (OFF_G2  + 128)
#define OFF_BF2  (OFF_BE2 + 128)
#define OFF_BF1  (OFF_BF2 + 128)         // 512
#define OFF_POL  (OFF_BF1 + 512)         // polar tile [6][64]
#define OFF_MU   (OFF_POL + 384)
#define OFF_RS   (OFF_MU  + 64)
#define SMEM_FLOATS (OFF_RS + 64)        // = 48448 floats
#define SMEM_BYTES  (SMEM_FLOATS * 4)    // = 193792 bytes

// GEMM microkernel: acc[4 tokens][8 cols] += src[64x128] @ W[128x128-cols]
// W streamed through smem in 32-row chunks. ldW = global row stride of W.
__device__ __forceinline__ void gemm_acc(
    const float* __restrict__ Wg, int ldW,
    const float* __restrict__ src, float* __restrict__ Wsh,
    float (&acc)[4][8], int tid, int t0, int c0)
{
    for (int kk = 0; kk < 128; kk += 32) {
        __syncthreads();  // prior Wsh readers done
        #pragma unroll
        for (int i = tid; i < 1024; i += NTHREADS) {
            int flat = i << 2;
            int r = flat >> 7;
            int c = flat & 127;
            *(float4*)(Wsh + flat) = *(const float4*)(Wg + (kk + r) * ldW + c);
        }
        __syncthreads();
        #pragma unroll 4
        for (int k = 0; k < 32; ++k) {
            float xv[4];
            #pragma unroll
            for (int j = 0; j < 4; ++j) xv[j] = src[(t0 + j) * PAD + kk + k];
            float4 wa = *(const float4*)(Wsh + k * 128 + c0);
            float4 wb = *(const float4*)(Wsh + k * 128 + c0 + 4);
            float w[8] = {wa.x, wa.y, wa.z, wa.w, wb.x, wb.y, wb.z, wb.w};
            #pragma unroll
            for (int j = 0; j < 4; ++j)
                #pragma unroll
                for (int i = 0; i < 8; ++i)
                    acc[j][i] = fmaf(xv[j], w[i], acc[j][i]);
        }
    }
    __syncthreads();
}

__device__ __forceinline__ void gemm_store(
    const float* __restrict__ Wg, int ldW,
    const float* __restrict__ src, float* __restrict__ dst,
    const float* __restrict__ bias_s, const float* __restrict__ res,
    float* __restrict__ Wsh, int tid, int t0, int c0)
{
    float acc[4][8];
    #pragma unroll
    for (int j = 0; j < 4; ++j)
        #pragma unroll
        for (int i = 0; i < 8; ++i) acc[j][i] = 0.f;

    gemm_acc(Wg, ldW, src, Wsh, acc, tid, t0, c0);

    #pragma unroll
    for (int j = 0; j < 4; ++j)
        #pragma unroll
        for (int i = 0; i < 8; ++i) {
            float v = acc[j][i] + bias_s[c0 + i];
            if (res) v += res[(t0 + j) * PAD + c0 + i];
            dst[(t0 + j) * PAD + c0 + i] = v;
        }
}

__global__ void __launch_bounds__(NTHREADS, 1)
polar_attention_kernel(
    const float* __restrict__ x,   const float* __restrict__ polar,
    const float* __restrict__ Wq,  const float* __restrict__ bq,
    const float* __restrict__ Wk,  const float* __restrict__ bk,
    const float* __restrict__ Wv,  const float* __restrict__ bv,
    const float* __restrict__ Wp,  const float* __restrict__ bp,
    const float* __restrict__ Wo,  const float* __restrict__ bo,
    const float* __restrict__ g1,  const float* __restrict__ be1,
    const float* __restrict__ g2,  const float* __restrict__ be2,
    const float* __restrict__ W1,  const float* __restrict__ bf1,
    const float* __restrict__ W2,  const float* __restrict__ bf2,
    float* __restrict__ out)
{
    extern __shared__ float sm[];
    float* A   = sm + OFF_A;
    float* Bx  = sm + OFF_B;
    float* Qb  = sm + OFF_Q;
    float* Kb  = sm + OFF_K;
    float* Vb  = sm + OFF_V;
    float* Wsh = sm + OFF_WSH;
    float* sWp = sm + OFF_WP;
    float* sPol= sm + OFF_POL;
    float* sMu = sm + OFF_MU;
    float* sRs = sm + OFF_RS;

    const int tid = threadIdx.x;
    const int n0  = blockIdx.x * TOK;
    const int b   = n0 / SS;
    const int s0  = n0 % SS;

    const float* xg = x + (b * CC) * SS + s0;         // + c*SS + t

    // ---- stage small params ----
    for (int i = tid; i < 768; i += NTHREADS) sWp[i] = Wp[i];
    for (int i = tid; i < 512; i += NTHREADS) sm[OFF_BF1 + i] = bf1[i];
    if (tid < 128) {
        sm[OFF_BQ  + tid] = bq[tid];
        sm[OFF_BK  + tid] = bk[tid];
        sm[OFF_BV  + tid] = bv[tid];
        sm[OFF_BP  + tid] = bp[tid];
        sm[OFF_BO  + tid] = bo[tid];
        sm[OFF_G1  + tid] = g1[tid];
        sm[OFF_BE1 + tid] = be1[tid];
        sm[OFF_G2  + tid] = g2[tid];
        sm[OFF_BE2 + tid] = be2[tid];
        sm[OFF_BF2 + tid] = bf2[tid];
    }

    // ---- load x tile (coalesced) ----
    for (int idx = tid; idx < TOK * CC; idx += NTHREADS) {
        int c = idx >> 6;
        int t = idx & 63;
        A[t * PAD + c] = xg[c * SS + t];
    }
    // ---- load polar tile as [p][t] (coalesced) ----
    for (int i = tid; i < PCH * TOK; i += NTHREADS) {
        int p = i >> 6;
        int t = i & 63;
        sPol[p * 64 + t] = polar[(b * PCH + p) * SS + s0 + t];
    }
    __syncthreads();

    // ---- x_with_polar = x + polar @ Wp + bp  (into A = residual1) ----
    for (int idx = tid; idx < TOK * CC; idx += NTHREADS) {
        int t = idx & 63;
        int c = idx >> 6;
        float v = A[t * PAD + c];
        #pragma unroll
        for (int p = 0; p < PCH; ++p)
            v = fmaf(sPol[p * 64 + t], sWp[p * 128 + c], v);
        A[t * PAD + c] = v + sm[OFF_BP + c];
    }
    __syncthreads();

    // ---- LayerNorm 1 (A -> Bx) ----
    if (tid < TOK) {
        float s = 0.f, sq = 0.f;
        #pragma unroll 8
        for (int c = 0; c < CC; ++c) {
            float v = A[tid * PAD + c];
            s += v; sq += v * v;
        }
        float m = s * (1.f / CC);
        float var = sq * (1.f / CC) - m * m;
        sMu[tid] = m;
        sRs[tid] = rsqrtf(var + 1e-5f);
    }
    __syncthreads();
    for (int idx = tid; idx < TOK * CC; idx += NTHREADS) {
        int t = idx & 63;
        int c = idx >> 6;
        Bx[t * PAD + c] = (A[t * PAD + c] - sMu[t]) * sRs[t] * sm[OFF_G1 + c] + sm[OFF_BE1 + c];
    }
    // (gemm_acc begins with __syncthreads)

    const int t0 = (tid >> 4) * 4;   // 16 token groups of 4
    const int c0 = (tid & 15) * 8;   // 16 col groups of 8

    // ---- Q,K,V = xn @ W + b ----
    gemm_store(Wq, 128, Bx, Qb, sm + OFF_BQ, nullptr, Wsh, tid, t0, c0);
    gemm_store(Wk, 128, Bx, Kb, sm + OFF_BK, nullptr, Wsh, tid, t0, c0);
    gemm_store(Wv, 128, Bx, Vb, sm + OFF_BV, nullptr, Wsh, tid, t0, c0);
    __syncthreads();

    // ---- per-token cross-head attention (one thread per token) -> Bx ----
    if (tid < TOK) {
        const int t = tid;
        float sc[NHEAD][NHEAD];
        const float scale = 0.25f;   // 1/sqrt(16)
        #pragma unroll
        for (int h = 0; h < NHEAD; ++h)
            #pragma unroll
            for (int g = 0; g < NHEAD; ++g) {
                float s = 0.f;
                #pragma unroll
                for (int d = 0; d < HDIM; ++d)
                    s = fmaf(Qb[t * PAD + h * HDIM + d], Kb[t * PAD + g * HDIM + d], s);
                sc[h][g] = s * scale;
            }
        #pragma unroll
        for (int h = 0; h < NHEAD; ++h) {
            float mx = sc[h][0];
            #pragma unroll
            for (int g = 1; g < NHEAD; ++g) mx = fmaxf(mx, sc[h][g]);
            float sum = 0.f;
            #pragma unroll
            for (int g = 0; g < NHEAD; ++g) {
                float e = expf(sc[h][g] - mx);
                sc[h][g] = e;
                sum += e;
            }
            float inv = 1.f / sum;
            #pragma unroll
            for (int g = 0; g < NHEAD; ++g) sc[h][g] *= inv;
        }
        #pragma unroll
        for (int h = 0; h < NHEAD; ++h)
            #pragma unroll
            for (int d = 0; d < HDIM; ++d) {
                float a = 0.f;
                #pragma unroll
                for (int g = 0; g < NHEAD; ++g)
                    a = fmaf(sc[h][g], Vb[t * PAD + g * HDIM + d], a);
                Bx[t * PAD + h * HDIM + d] = a;
            }
    }
    __syncthreads();

    // ---- out1 = attended @ Wo + bo + residual1  (into A) ----
    gemm_store(Wo, 128, Bx, A, sm + OFF_BO, A, Wsh, tid, t0, c0);
    __syncthreads();

    // ---- LayerNorm 2 (A -> Bx) ----
    if (tid < TOK) {
        float s = 0.f, sq = 0.f;
        #pragma unroll 8
        for (int c = 0; c < CC; ++c) {
            float v = A[tid * PAD + c];
            s += v; sq += v * v;
        }
        float m = s * (1.f / CC);
        float var = sq * (1.f / CC) - m * m;
        sMu[tid] = m;
        sRs[tid] = rsqrtf(var + 1e-5f);
    }
    __syncthreads();
    for (int idx = tid; idx < TOK * CC; idx += NTHREADS) {
        int t = idx & 63;
        int c = idx >> 6;
        Bx[t * PAD + c] = (A[t * PAD + c] - sMu[t]) * sRs[t] * sm[OFF_G2 + c] + sm[OFF_BE2 + c];
    }

    // ---- FFN: out2 = relu(h @ W1 + bf1) @ W2 + bf2 + out1 ----
    float acc2[4][8];
    #pragma unroll
    for (int j = 0; j < 4; ++j)
        #pragma unroll
        for (int i = 0; i < 8; ++i) acc2[j][i] = 0.f;

    for (int j0 = 0; j0 < 512; j0 += 128) {
        float h1[4][8];
        #pragma unroll
        for (int j = 0; j < 4; ++j)
            #pragma unroll
            for (int i = 0; i < 8; ++i) h1[j][i] = 0.f;

        gemm_acc(W1 + j0, 512, Bx, Wsh, h1, tid, t0, c0);   // h1 chunk [64 x 128]

        #pragma unroll
        for (int j = 0; j < 4; ++j)
            #pragma unroll
            for (int i = 0; i < 8; ++i)
                Qb[(t0 + j) * PAD + c0 + i] =
                    fmaxf(h1[j][i] + sm[OFF_BF1 + j0 + c0 + i], 0.f);
        __syncthreads();

        gemm_acc(W2 + j0 * 128, 128, Qb, Wsh, acc2, tid, t0, c0);
    }

    #pragma unroll
    for (int j = 0; j < 4; ++j)
        #pragma unroll
        for (int i = 0; i < 8; ++i)
            Bx[(t0 + j) * PAD + c0 + i] =
                acc2[j][i] + sm[OFF_BF2 + c0 + i] + A[(t0 + j) * PAD + c0 + i];
    __syncthreads();

    // ---- coalesced global store ----
    float* og = out + (b * CC) * SS + s0;
    for (int idx = tid; idx < TOK * CC; idx += NTHREADS) {
        int c = idx >> 6;
        int t = idx & 63;
        og[c * SS + t] = Bx[t * PAD + c];
    }
}

extern "C" void kernel_launch(void* const* d_in, const int* in_sizes, int n_in,
                              void* d_out, int out_size)
{
    (void)in_sizes; (void)n_in; (void)out_size;
    cudaFuncSetAttribute(polar_attention_kernel,
                         cudaFuncAttributeMaxDynamicSharedMemorySize, SMEM_BYTES);

    const float* x     = (const float*)d_in[0];
    const float* polar = (const float*)d_in[1];
    const float* Wq    = (const float*)d_in[2];
    const float* bq    = (const float*)d_in[3];
    const float* Wk    = (const float*)d_in[4];
    const float* bk    = (const float*)d_in[5];
    const float* Wv    = (const float*)d_in[6];
    const float* bv    = (const float*)d_in[7];
    const float* Wp    = (const float*)d_in[8];
    const float* bp    = (const float*)d_in[9];
    const float* Wo    = (const float*)d_in[10];
    const float* bo    = (const float*)d_in[11];
    const float* g1    = (const float*)d_in[12];
    const float* be1   = (const float*)d_in[13];
    const float* g2    = (const float*)d_in[14];
    const float* be2   = (const float*)d_in[15];
    const float* W1    = (const float*)d_in[16];
    const float* bf1   = (const float*)d_in[17];
    const float* W2    = (const float*)d_in[18];
    const float* bf2   = (const float*)d_in[19];
    float* out = (float*)d_out;

    dim3 grid(NTOK / TOK);   // 4096 CTAs
    polar_attention_kernel<<<grid, NTHREADS, SMEM_BYTES>>>(
        x, polar, Wq, bq, Wk, bk, Wv, bv, Wp, bp, Wo, bo,
        g1, be1, g2, be2, W1, bf1, W2, bf2, out);
}

// round 2
// speedup vs baseline: 1.1350x; 1.1350x over previous
#include <cuda_runtime.h>

typedef unsigned long long ull;

// Problem constants
#define CC   128
#define PCH  6
#define SS   131072
#define NB   2
#define NTOK (NB*SS)
#define TOK  64
#define PAD  132          // multiple of 4 -> 16B-aligned rows for float4/float2 LDS
#define NTHREADS 256
#define NHEAD 8
#define HDIM  16

// ---- shared memory layout (float offsets, all 16B aligned) ----
#define ROWF (TOK*PAD)                   // 8448
#define OFF_A    0                       // residual1 / out1        [64][132]
#define OFF_B    (ROWF)                  // xn / attended / out2    [64][132]
#define OFF_Q    (2*ROWF)                // Q / relu(h) chunk       [64][132]
#define OFF_K    (3*ROWF)                // K
#define OFF_V    (4*ROWF)                // V
#define OFF_WSH  (5*ROWF)                // weight staging, double buffer 2x(32x128)
#define OFF_WP   (OFF_WSH + 8192)        // Wp 6x128
#define OFF_BQ   (OFF_WP  + 768)
#define OFF_BK   (OFF_BQ  + 128)
#define OFF_BV   (OFF_BK  + 128)
#define OFF_BP   (OFF_BV  + 128)
#define OFF_BO   (OFF_BP  + 128)
#define OFF_G1   (OFF_BO  + 128)
#define OFF_BE1  (OFF_G1  + 128)
#define OFF_G2   (OFF_BE1 + 128)
#define OFF_BE2  (OFF_G2  + 128)
#define OFF_BF2  (OFF_BE2 + 128)
#define OFF_BF1  (OFF_BF2 + 128)         // 512
#define OFF_POL  (OFF_BF1 + 512)         // polar [6][64]
#define SMEM_FLOATS (OFF_POL + 384)
#define SMEM_BYTES  (SMEM_FLOATS * 4)    // 213,760 B

// ---- packed f32x2 primitives ----
__device__ __forceinline__ void fma2(ull& d, ull a, ull b) {
    asm("fma.rn.f32x2 %0, %1, %2, %0;" : "+l"(d) : "l"(a), "l"(b));
}
__device__ __forceinline__ ull add2(ull a, ull b) {
    ull r; asm("add.rn.f32x2 %0, %1, %2;" : "=l"(r) : "l"(a), "l"(b)); return r;
}
__device__ __forceinline__ ull dup2(float x) {
    ull r; asm("mov.b64 %0, {%1, %1};" : "=l"(r) : "f"(x)); return r;
}
__device__ __forceinline__ float2 unpk(ull v) {
    float2 f; asm("mov.b64 {%0, %1}, %2;" : "=f"(f.x), "=f"(f.y) : "l"(v)); return f;
}

// ---- cp.async helpers ----
#define CP_WAIT(N) asm volatile("cp.async.wait_group %0;" :: "n"(N) : "memory")

__device__ __forceinline__ void stage_copy(float* buf, const float* __restrict__ Wg,
                                           int ldW, int kk, int tid)
{
    #pragma unroll
    for (int it = 0; it < 4; ++it) {
        int flat = (tid + it * NTHREADS) * 4;
        int r = flat >> 7, c = flat & 127;
        unsigned dst = (unsigned)__cvta_generic_to_shared(buf + flat);
        const float* src = Wg + (kk + r) * ldW + c;
        asm volatile("cp.async.ca.shared.global [%0], [%1], 16;" :: "r"(dst), "l"(src) : "memory");
    }
    asm volatile("cp.async.commit_group;" ::: "memory");
}

// GEMM: acc[4 tok][4 colpairs] += src[64x128] @ W[128 x (c0..c0+7)]
__device__ __forceinline__ void gemm_acc(
    const float* __restrict__ Wg, int ldW,
    const float* __restrict__ src, float* __restrict__ Wsh,
    ull (&acc)[4][4], int tid, int t0, int c0)
{
    stage_copy(Wsh, Wg, ldW, 0, tid);
    #pragma unroll
    for (int s = 0; s < 4; ++s) {
        if (s < 3) { stage_copy(Wsh + ((s + 1) & 1) * 4096, Wg, ldW, (s + 1) * 32, tid); CP_WAIT(1); }
        else       { CP_WAIT(0); }
        __syncthreads();
        const float* wb = Wsh + (s & 1) * 4096;
        const float* xb = src + s * 32;
        #pragma unroll
        for (int k4 = 0; k4 < 32; k4 += 4) {
            float4 xv[4];
            #pragma unroll
            for (int j = 0; j < 4; ++j)
                xv[j] = *(const float4*)(xb + (t0 + j) * PAD + k4);
            #pragma unroll
            for (int q = 0; q < 4; ++q) {
                const ull* wr = (const ull*)(wb + (k4 + q) * 128 + c0);
                ull w0 = wr[0], w1 = wr[1], w2 = wr[2], w3 = wr[3];
                #pragma unroll
                for (int j = 0; j < 4; ++j) {
                    float xs = (q == 0) ? xv[j].x : (q == 1) ? xv[j].y : (q == 2) ? xv[j].z : xv[j].w;
                    ull xd = dup2(xs);
                    fma2(acc[j][0], xd, w0);
                    fma2(acc[j][1], xd, w1);
                    fma2(acc[j][2], xd, w2);
                    fma2(acc[j][3], xd, w3);
                }
            }
        }
        __syncthreads();
    }
}

__device__ __forceinline__ void gemm_store(
    const float* __restrict__ Wg, int ldW,
    const float* __restrict__ src, float* __restrict__ dst,
    const float* __restrict__ bias_s, const float* __restrict__ res,
    float* __restrict__ Wsh, int tid, int t0, int c0)
{
    ull acc[4][4];
    #pragma unroll
    for (int j = 0; j < 4; ++j)
        #pragma unroll
        for (int i = 0; i < 4; ++i) acc[j][i] = 0ull;

    gemm_acc(Wg, ldW, src, Wsh, acc, tid, t0, c0);

    const ull* b2 = (const ull*)(bias_s + c0);
    #pragma unroll
    for (int j = 0; j < 4; ++j) {
        ull* d = (ull*)(dst + (t0 + j) * PAD + c0);
        const ull* r = res ? (const ull*)(res + (t0 + j) * PAD + c0) : nullptr;
        #pragma unroll
        for (int i = 0; i < 4; ++i) {
            ull v = add2(acc[j][i], b2[i]);
            if (r) v = add2(v, r[i]);
            d[i] = v;
        }
    }
}

// LayerNorm: 4 threads per token, warp-shuffle reduction, float4 vector IO
__device__ __forceinline__ void layernorm(
    const float* __restrict__ A, float* __restrict__ Bx,
    const float* __restrict__ g, const float* __restrict__ be, int tid)
{
    int t = tid >> 2, q = tid & 3;
    const float4* rowA = (const float4*)(A + t * PAD + q * 32);
    float s = 0.f, sq = 0.f;
    float4 v[8];
    #pragma unroll
    for (int i = 0; i < 8; ++i) {
        v[i] = rowA[i];
        s  += v[i].x + v[i].y + v[i].z + v[i].w;
        sq += v[i].x * v[i].x + v[i].y * v[i].y + v[i].z * v[i].z + v[i].w * v[i].w;
    }
    s  += __shfl_xor_sync(0xffffffffu, s, 1);
    sq += __shfl_xor_sync(0xffffffffu, sq, 1);
    s  += __shfl_xor_sync(0xffffffffu, s, 2);
    sq += __shfl_xor_sync(0xffffffffu, sq, 2);
    float m = s * (1.f / CC);
    float rs = rsqrtf(sq * (1.f / CC) - m * m + 1e-5f);

    const float4* g4  = (const float4*)(g  + q * 32);
    const float4* be4 = (const float4*)(be + q * 32);
    float4* rowB = (float4*)(Bx + t * PAD + q * 32);
    #pragma unroll
    for (int i = 0; i < 8; ++i) {
        float4 gg = g4[i], bb = be4[i], o;
        o.x = (v[i].x - m) * rs * gg.x + bb.x;
        o.y = (v[i].y - m) * rs * gg.y + bb.y;
        o.z = (v[i].z - m) * rs * gg.z + bb.z;
        o.w = (v[i].w - m) * rs * gg.w + bb.w;
        rowB[i] = o;
    }
}

__global__ void __launch_bounds__(NTHREADS, 1)
polar_attention_kernel(
    const float* __restrict__ x,   const float* __restrict__ polar,
    const float* __restrict__ Wq,  const float* __restrict__ bq,
    const float* __restrict__ Wk,  const float* __restrict__ bk,
    const float* __restrict__ Wv,  const float* __restrict__ bv,
    const float* __restrict__ Wp,  const float* __restrict__ bp,
    const float* __restrict__ Wo,  const float* __restrict__ bo,
    const float* __restrict__ g1,  const float* __restrict__ be1,
    const float* __restrict__ g2,  const float* __restrict__ be2,
    const float* __restrict__ W1,  const float* __restrict__ bf1,
    const float* __restrict__ W2,  const float* __restrict__ bf2,
    float* __restrict__ out)
{
    extern __shared__ float sm[];
    float* A   = sm + OFF_A;
    float* Bx  = sm + OFF_B;
    float* Qb  = sm + OFF_Q;
    float* Kb  = sm + OFF_K;
    float* Vb  = sm + OFF_V;
    float* Wsh = sm + OFF_WSH;
    float* sWp = sm + OFF_WP;
    float* sPol= sm + OFF_POL;

    const int tid = threadIdx.x;
    const int n0  = blockIdx.x * TOK;
    const int b   = n0 / SS;
    const int s0  = n0 % SS;

    const float* xg = x + (b * CC) * SS + s0;

    // ---- stage small params ----
    for (int i = tid; i < 768; i += NTHREADS) sWp[i] = Wp[i];
    for (int i = tid; i < 512; i += NTHREADS) sm[OFF_BF1 + i] = bf1[i];
    if (tid < 128) {
        sm[OFF_BQ  + tid] = bq[tid];
        sm[OFF_BK  + tid] = bk[tid];
        sm[OFF_BV  + tid] = bv[tid];
        sm[OFF_BP  + tid] = bp[tid];
        sm[OFF_BO  + tid] = bo[tid];
        sm[OFF_G1  + tid] = g1[tid];
        sm[OFF_BE1 + tid] = be1[tid];
        sm[OFF_G2  + tid] = g2[tid];
        sm[OFF_BE2 + tid] = be2[tid];
        sm[OFF_BF2 + tid] = bf2[tid];
    }

    // ---- load x tile (coalesced gmem reads) ----
    for (int idx = tid; idx < TOK * CC; idx += NTHREADS) {
        int c = idx >> 6;
        int t = idx & 63;
        A[t * PAD + c] = xg[c * SS + t];
    }
    for (int i = tid; i < PCH * TOK; i += NTHREADS) {
        int p = i >> 6;
        int t = i & 63;
        sPol[p * 64 + t] = polar[(b * PCH + p) * SS + s0 + t];
    }
    __syncthreads();

    // ---- x_with_polar = x + polar @ Wp + bp (into A, vectorized) ----
    for (int idx = tid; idx < TOK * 32; idx += NTHREADS) {
        int t = idx >> 5;
        int c4 = (idx & 31) * 4;
        float4 v = *(const float4*)(A + t * PAD + c4);
        #pragma unroll
        for (int p = 0; p < PCH; ++p) {
            float pv = sPol[p * 64 + t];
            float4 w = *(const float4*)(sWp + p * 128 + c4);
            v.x = fmaf(pv, w.x, v.x); v.y = fmaf(pv, w.y, v.y);
            v.z = fmaf(pv, w.z, v.z); v.w = fmaf(pv, w.w, v.w);
        }
        float4 bb = *(const float4*)(sm + OFF_BP + c4);
        v.x += bb.x; v.y += bb.y; v.z += bb.z; v.w += bb.w;
        *(float4*)(A + t * PAD + c4) = v;
    }
    __syncthreads();

    // ---- LayerNorm 1 (A -> Bx) ----
    layernorm(A, Bx, sm + OFF_G1, sm + OFF_BE1, tid);

    const int t0 = (tid >> 4) * 4;
    const int c0 = (tid & 15) * 8;

    // ---- Q,K,V ----
    gemm_store(Wq, 128, Bx, Qb, sm + OFF_BQ, nullptr, Wsh, tid, t0, c0);
    gemm_store(Wk, 128, Bx, Kb, sm + OFF_BK, nullptr, Wsh, tid, t0, c0);
    gemm_store(Wv, 128, Bx, Vb, sm + OFF_BV, nullptr, Wsh, tid, t0, c0);
    __syncthreads();

    // ---- per-token cross-head attention: 4 threads/token, 2 heads each -> Bx ----
    {
        const int t  = tid >> 2;
        const int h0 = (tid & 3) * 2;
        const float* Qr = Qb + t * PAD;
        const float* Kr = Kb + t * PAD;
        const float* Vr = Vb + t * PAD;
        float sc[2][NHEAD];
        const float scale = 0.25f;
        #pragma unroll
        for (int hh = 0; hh < 2; ++hh) {
            float q[HDIM];
            #pragma unroll
            for (int d = 0; d < HDIM; ++d) q[d] = Qr[(h0 + hh) * HDIM + d];
            #pragma unroll
            for (int g = 0; g < NHEAD; ++g) {
                float s = 0.f;
                #pragma unroll
                for (int d = 0; d < HDIM; ++d)
                    s = fmaf(q[d], Kr[g * HDIM + d], s);
                sc[hh][g] = s * scale;
            }
            float mx = sc[hh][0];
            #pragma unroll
            for (int g = 1; g < NHEAD; ++g) mx = fmaxf(mx, sc[hh][g]);
            float sum = 0.f;
            #pragma unroll
            for (int g = 0; g < NHEAD; ++g) {
                float e = __expf(sc[hh][g] - mx);
                sc[hh][g] = e; sum += e;
            }
            float inv = 1.f / sum;
            #pragma unroll
            for (int g = 0; g < NHEAD; ++g) sc[hh][g] *= inv;
        }
        #pragma unroll
        for (int hh = 0; hh < 2; ++hh)
            #pragma unroll
            for (int d = 0; d < HDIM; ++d) {
                float a = 0.f;
                #pragma unroll
                for (int g = 0; g < NHEAD; ++g)
                    a = fmaf(sc[hh][g], Vr[g * HDIM + d], a);
                Bx[t * PAD + (h0 + hh) * HDIM + d] = a;
            }
    }
    __syncthreads();

    // ---- out1 = attended @ Wo + bo + residual1 (into A) ----
    gemm_store(Wo, 128, Bx, A, sm + OFF_BO, A, Wsh, tid, t0, c0);
    __syncthreads();

    // ---- LayerNorm 2 (A -> Bx) ----
    layernorm(A, Bx, sm + OFF_G2, sm + OFF_BE2, tid);

    // ---- FFN ----
    ull acc2[4][4];
    #pragma unroll
    for (int j = 0; j < 4; ++j)
        #pragma unroll
        for (int i = 0; i < 4; ++i) acc2[j][i] = 0ull;

    #pragma unroll 1
    for (int j0 = 0; j0 < 512; j0 += 128) {
        ull h1[4][4];
        #pragma unroll
        for (int j = 0; j < 4; ++j)
            #pragma unroll
            for (int i = 0; i < 4; ++i) h1[j][i] = 0ull;

        gemm_acc(W1 + j0, 512, Bx, Wsh, h1, tid, t0, c0);

        const ull* bf = (const ull*)(sm + OFF_BF1 + j0 + c0);
        #pragma unroll
        for (int j = 0; j < 4; ++j) {
            float2* q = (float2*)(Qb + (t0 + j) * PAD + c0);
            #pragma unroll
            for (int i = 0; i < 4; ++i) {
                float2 f = unpk(add2(h1[j][i], bf[i]));
                q[i] = make_float2(fmaxf(f.x, 0.f), fmaxf(f.y, 0.f));
            }
        }
        gemm_acc(W2 + j0 * 128, 128, Qb, Wsh, acc2, tid, t0, c0);
    }

    const ull* bf2s = (const ull*)(sm + OFF_BF2 + c0);
    #pragma unroll
    for (int j = 0; j < 4; ++j) {
        ull* d = (ull*)(Bx + (t0 + j) * PAD + c0);
        const ull* r = (const ull*)(A + (t0 + j) * PAD + c0);
        #pragma unroll
        for (int i = 0; i < 4; ++i)
            d[i] = add2(add2(acc2[j][i], bf2s[i]), r[i]);
    }
    __syncthreads();

    // ---- coalesced global store ----
    float* og = out + (b * CC) * SS + s0;
    for (int idx = tid; idx < TOK * CC; idx += NTHREADS) {
        int c = idx >> 6;
        int t = idx & 63;
        og[c * SS + t] = Bx[t * PAD + c];
    }
}

extern "C" void kernel_launch(void* const* d_in, const int* in_sizes, int n_in,
                              void* d_out, int out_size)
{
    (void)in_sizes; (void)n_in; (void)out_size;
    cudaFuncSetAttribute(polar_attention_kernel,
                         cudaFuncAttributeMaxDynamicSharedMemorySize, SMEM_BYTES);

    const float* x     = (const float*)d_in[0];
    const float* polar = (const float*)d_in[1];
    const float* Wq    = (const float*)d_in[2];
    const float* bq    = (const float*)d_in[3];
    const float* Wk    = (const float*)d_in[4];
    const float* bk    = (const float*)d_in[5];
    const float* Wv    = (const float*)d_in[6];
    const float* bv    = (const float*)d_in[7];
    const float* Wp    = (const float*)d_in[8];
    const float* bp    = (const float*)d_in[9];
    const float* Wo    = (const float*)d_in[10];
    const float* bo    = (const float*)d_in[11];
    const float* g1    = (const float*)d_in[12];
    const float* be1   = (const float*)d_in[13];
    const float* g2    = (const float*)d_in[14];
    const float* be2   = (const float*)d_in[15];
    const float* W1    = (const float*)d_in[16];
    const float* bf1   = (const float*)d_in[17];
    const float* W2    = (const float*)d_in[18];
    const float* bf2   = (const float*)d_in[19];
    float* out = (float*)d_out;

    dim3 grid(NTOK / TOK);
    polar_attention_kernel<<<grid, NTHREADS, SMEM_BYTES>>>(
        x, polar, Wq, bq, Wk, bk, Wv, bv, Wp, bp, Wo, bo,
        g1, be1, g2, be2, W1, bf1, W2, bf2, out);
}

// round 3
// speedup vs baseline: 1.1377x; 1.0024x over previous
#include <cuda_runtime.h>

typedef unsigned long long ull;

// Problem constants
#define CC   128
#define PCH  6
#define SS   131072
#define NB   2
#define NTOK (NB*SS)
#define TOK  64
#define PAD  132          // multiple of 4 -> 16B-aligned rows for float4/float2 LDS
#define NTHREADS 256
#define NHEAD 8
#define HDIM  16

// ---- shared memory layout (float offsets, all 16B aligned) ----
#define ROWF (TOK*PAD)                   // 8448
#define OFF_A    0                       // residual1 / out1        [64][132]
#define OFF_B    (ROWF)                  // xn / attended / out2    [64][132]
#define OFF_Q    (2*ROWF)                // Q / relu(h) chunk       [64][132]
#define OFF_K    (3*ROWF)                // K
#define OFF_V    (4*ROWF)                // V
#define OFF_WSH  (5*ROWF)                // weight staging, double buffer 2x(32x128)
#define OFF_WP   (OFF_WSH + 8192)        // Wp 6x128
#define OFF_BQ   (OFF_WP  + 768)
#define OFF_BK   (OFF_BQ  + 128)
#define OFF_BV   (OFF_BK  + 128)
#define OFF_BP   (OFF_BV  + 128)
#define OFF_BO   (OFF_BP  + 128)
#define OFF_G1   (OFF_BO  + 128)
#define OFF_BE1  (OFF_G1  + 128)
#define OFF_G2   (OFF_BE1 + 128)
#define OFF_BE2  (OFF_G2  + 128)
#define OFF_BF2  (OFF_BE2 + 128)
#define OFF_BF1  (OFF_BF2 + 128)         // 512
#define OFF_POL  (OFF_BF1 + 512)         // polar [6][64]
#define SMEM_FLOATS (OFF_POL + 384)
#define SMEM_BYTES  (SMEM_FLOATS * 4)    // 213,760 B

// ---- packed f32x2 primitives ----
__device__ __forceinline__ void fma2(ull& d, ull a, ull b) {
    asm("fma.rn.f32x2 %0, %1, %2, %0;" : "+l"(d) : "l"(a), "l"(b));
}
__device__ __forceinline__ ull add2(ull a, ull b) {
    ull r; asm("add.rn.f32x2 %0, %1, %2;" : "=l"(r) : "l"(a), "l"(b)); return r;
}
__device__ __forceinline__ ull dup2(float x) {
    ull r; asm("mov.b64 %0, {%1, %1};" : "=l"(r) : "f"(x)); return r;
}
__device__ __forceinline__ float2 unpk(ull v) {
    float2 f; asm("mov.b64 {%0, %1}, %2;" : "=f"(f.x), "=f"(f.y) : "l"(v)); return f;
}

// ---- cp.async helpers ----
#define CP_WAIT(N) asm volatile("cp.async.wait_group %0;" :: "n"(N) : "memory")

__device__ __forceinline__ void stage_copy(float* buf, const float* __restrict__ Wg,
                                           int ldW, int kk, int tid)
{
    #pragma unroll
    for (int it = 0; it < 4; ++it) {
        int flat = (tid + it * NTHREADS) * 4;
        int r = flat >> 7, c = flat & 127;
        unsigned dst = (unsigned)__cvta_generic_to_shared(buf + flat);
        const float* src = Wg + (kk + r) * ldW + c;
        asm volatile("cp.async.ca.shared.global [%0], [%1], 16;" :: "r"(dst), "l"(src) : "memory");
    }
    asm volatile("cp.async.commit_group;" ::: "memory");
}

// GEMM: acc[4 tok][4 colpairs] += src[64x128] @ W[128 x (c0..c0+7)]
__device__ __forceinline__ void gemm_acc(
    const float* __restrict__ Wg, int ldW,
    const float* __restrict__ src, float* __restrict__ Wsh,
    ull (&acc)[4][4], int tid, int t0, int c0)
{
    stage_copy(Wsh, Wg, ldW, 0, tid);
    #pragma unroll
    for (int s = 0; s < 4; ++s) {
        if (s < 3) { stage_copy(Wsh + ((s + 1) & 1) * 4096, Wg, ldW, (s + 1) * 32, tid); CP_WAIT(1); }
        else       { CP_WAIT(0); }
        __syncthreads();
        const float* wb = Wsh + (s & 1) * 4096;
        const float* xb = src + s * 32;
        #pragma unroll
        for (int k4 = 0; k4 < 32; k4 += 4) {
            float4 xv[4];
            #pragma unroll
            for (int j = 0; j < 4; ++j)
                xv[j] = *(const float4*)(xb + (t0 + j) * PAD + k4);
            #pragma unroll
            for (int q = 0; q < 4; ++q) {
                const ull* wr = (const ull*)(wb + (k4 + q) * 128 + c0);
                ull w0 = wr[0], w1 = wr[1], w2 = wr[2], w3 = wr[3];
                #pragma unroll
                for (int j = 0; j < 4; ++j) {
                    float xs = (q == 0) ? xv[j].x : (q == 1) ? xv[j].y : (q == 2) ? xv[j].z : xv[j].w;
                    ull xd = dup2(xs);
                    fma2(acc[j][0], xd, w0);
                    fma2(acc[j][1], xd, w1);
                    fma2(acc[j][2], xd, w2);
                    fma2(acc[j][3], xd, w3);
                }
            }
        }
        __syncthreads();
    }
}

__device__ __forceinline__ void gemm_store(
    const float* __restrict__ Wg, int ldW,
    const float* __restrict__ src, float* __restrict__ dst,
    const float* __restrict__ bias_s, const float* __restrict__ res,
    float* __restrict__ Wsh, int tid, int t0, int c0)
{
    ull acc[4][4];
    #pragma unroll
    for (int j = 0; j < 4; ++j)
        #pragma unroll
        for (int i = 0; i < 4; ++i) acc[j][i] = 0ull;

    gemm_acc(Wg, ldW, src, Wsh, acc, tid, t0, c0);

    const ull* b2 = (const ull*)(bias_s + c0);
    #pragma unroll
    for (int j = 0; j < 4; ++j) {
        ull* d = (ull*)(dst + (t0 + j) * PAD + c0);
        const ull* r = res ? (const ull*)(res + (t0 + j) * PAD + c0) : nullptr;
        #pragma unroll
        for (int i = 0; i < 4; ++i) {
            ull v = add2(acc[j][i], b2[i]);
            if (r) v = add2(v, r[i]);
            d[i] = v;
        }
    }
}

// LayerNorm: 4 threads per token, warp-shuffle reduction, float4 vector IO
__device__ __forceinline__ void layernorm(
    const float* __restrict__ A, float* __restrict__ Bx,
    const float* __restrict__ g, const float* __restrict__ be, int tid)
{
    int t = tid >> 2, q = tid & 3;
    const float4* rowA = (const float4*)(A + t * PAD + q * 32);
    float s = 0.f, sq = 0.f;
    float4 v[8];
    #pragma unroll
    for (int i = 0; i < 8; ++i) {
        v[i] = rowA[i];
        s  += v[i].x + v[i].y + v[i].z + v[i].w;
        sq += v[i].x * v[i].x + v[i].y * v[i].y + v[i].z * v[i].z + v[i].w * v[i].w;
    }
    s  += __shfl_xor_sync(0xffffffffu, s, 1);
    sq += __shfl_xor_sync(0xffffffffu, sq, 1);
    s  += __shfl_xor_sync(0xffffffffu, s, 2);
    sq += __shfl_xor_sync(0xffffffffu, sq, 2);
    float m = s * (1.f / CC);
    float rs = rsqrtf(sq * (1.f / CC) - m * m + 1e-5f);

    const float4* g4  = (const float4*)(g  + q * 32);
    const float4* be4 = (const float4*)(be + q * 32);
    float4* rowB = (float4*)(Bx + t * PAD + q * 32);
    #pragma unroll
    for (int i = 0; i < 8; ++i) {
        float4 gg = g4[i], bb = be4[i], o;
        o.x = (v[i].x - m) * rs * gg.x + bb.x;
        o.y = (v[i].y - m) * rs * gg.y + bb.y;
        o.z = (v[i].z - m) * rs * gg.z + bb.z;
        o.w = (v[i].w - m) * rs * gg.w + bb.w;
        rowB[i] = o;
    }
}

__global__ void __launch_bounds__(NTHREADS, 1)
polar_attention_kernel(
    const float* __restrict__ x,   const float* __restrict__ polar,
    const float* __restrict__ Wq,  const float* __restrict__ bq,
    const float* __restrict__ Wk,  const float* __restrict__ bk,
    const float* __restrict__ Wv,  const float* __restrict__ bv,
    const float* __restrict__ Wp,  const float* __restrict__ bp,
    const float* __restrict__ Wo,  const float* __restrict__ bo,
    const float* __restrict__ g1,  const float* __restrict__ be1,
    const float* __restrict__ g2,  const float* __restrict__ be2,
    const float* __restrict__ W1,  const float* __restrict__ bf1,
    const float* __restrict__ W2,  const float* __restrict__ bf2,
    float* __restrict__ out)
{
    extern __shared__ float sm[];
    float* A   = sm + OFF_A;
    float* Bx  = sm + OFF_B;
    float* Qb  = sm + OFF_Q;
    float* Kb  = sm + OFF_K;
    float* Vb  = sm + OFF_V;
    float* Wsh = sm + OFF_WSH;
    float* sWp = sm + OFF_WP;
    float* sPol= sm + OFF_POL;

    const int tid = threadIdx.x;
    const int n0  = blockIdx.x * TOK;
    const int b   = n0 / SS;
    const int s0  = n0 % SS;

    const float* xg = x + (b * CC) * SS + s0;

    // ---- stage small params ----
    for (int i = tid; i < 768; i += NTHREADS) sWp[i] = Wp[i];
    for (int i = tid; i < 512; i += NTHREADS) sm[OFF_BF1 + i] = bf1[i];
    if (tid < 128) {
        sm[OFF_BQ  + tid] = bq[tid];
        sm[OFF_BK  + tid] = bk[tid];
        sm[OFF_BV  + tid] = bv[tid];
        sm[OFF_BP  + tid] = bp[tid];
        sm[OFF_BO  + tid] = bo[tid];
        sm[OFF_G1  + tid] = g1[tid];
        sm[OFF_BE1 + tid] = be1[tid];
        sm[OFF_G2  + tid] = g2[tid];
        sm[OFF_BE2 + tid] = be2[tid];
        sm[OFF_BF2 + tid] = bf2[tid];
    }

    // ---- load x tile (coalesced gmem reads) ----
    for (int idx = tid; idx < TOK * CC; idx += NTHREADS) {
        int c = idx >> 6;
        int t = idx & 63;
        A[t * PAD + c] = xg[c * SS + t];
    }
    for (int i = tid; i < PCH * TOK; i += NTHREADS) {
        int p = i >> 6;
        int t = i & 63;
        sPol[p * 64 + t] = polar[(b * PCH + p) * SS + s0 + t];
    }
    __syncthreads();

    // ---- x_with_polar = x + polar @ Wp + bp (into A, vectorized) ----
    for (int idx = tid; idx < TOK * 32; idx += NTHREADS) {
        int t = idx >> 5;
        int c4 = (idx & 31) * 4;
        float4 v = *(const float4*)(A + t * PAD + c4);
        #pragma unroll
        for (int p = 0; p < PCH; ++p) {
            float pv = sPol[p * 64 + t];
            float4 w = *(const float4*)(sWp + p * 128 + c4);
            v.x = fmaf(pv, w.x, v.x); v.y = fmaf(pv, w.y, v.y);
            v.z = fmaf(pv, w.z, v.z); v.w = fmaf(pv, w.w, v.w);
        }
        float4 bb = *(const float4*)(sm + OFF_BP + c4);
        v.x += bb.x; v.y += bb.y; v.z += bb.z; v.w += bb.w;
        *(float4*)(A + t * PAD + c4) = v;
    }
    __syncthreads();

    // ---- LayerNorm 1 (A -> Bx) ----
    layernorm(A, Bx, sm + OFF_G1, sm + OFF_BE1, tid);

    const int t0 = (tid >> 4) * 4;
    const int c0 = (tid & 15) * 8;

    // ---- Q,K,V ----
    gemm_store(Wq, 128, Bx, Qb, sm + OFF_BQ, nullptr, Wsh, tid, t0, c0);
    gemm_store(Wk, 128, Bx, Kb, sm + OFF_BK, nullptr, Wsh, tid, t0, c0);
    gemm_store(Wv, 128, Bx, Vb, sm + OFF_BV, nullptr, Wsh, tid, t0, c0);
    __syncthreads();

    // ---- per-token cross-head attention: 4 threads/token, 2 heads each -> Bx ----
    {
        const int t  = tid >> 2;
        const int h0 = (tid & 3) * 2;
        const float* Qr = Qb + t * PAD;
        const float* Kr = Kb + t * PAD;
        const float* Vr = Vb + t * PAD;
        float sc[2][NHEAD];
        const float scale = 0.25f;
        #pragma unroll
        for (int hh = 0; hh < 2; ++hh) {
            float q[HDIM];
            #pragma unroll
            for (int d = 0; d < HDIM; ++d) q[d] = Qr[(h0 + hh) * HDIM + d];
            #pragma unroll
            for (int g = 0; g < NHEAD; ++g) {
                float s = 0.f;
                #pragma unroll
                for (int d = 0; d < HDIM; ++d)
                    s = fmaf(q[d], Kr[g * HDIM + d], s);
                sc[hh][g] = s * scale;
            }
            float mx = sc[hh][0];
            #pragma unroll
            for (int g = 1; g < NHEAD; ++g) mx = fmaxf(mx, sc[hh][g]);
            float sum = 0.f;
            #pragma unroll
            for (int g = 0; g < NHEAD; ++g) {
                float e = __expf(sc[hh][g] - mx);
                sc[hh][g] = e; sum += e;
            }
            float inv = 1.f / sum;
            #pragma unroll
            for (int g = 0; g < NHEAD; ++g) sc[hh][g] *= inv;
        }
        #pragma unroll
        for (int hh = 0; hh < 2; ++hh)
            #pragma unroll
            for (int d = 0; d < HDIM; ++d) {
                float a = 0.f;
                #pragma unroll
                for (int g = 0; g < NHEAD; ++g)
                    a = fmaf(sc[hh][g], Vr[g * HDIM + d], a);
                Bx[t * PAD + (h0 + hh) * HDIM + d] = a;
            }
    }
    __syncthreads();

    // ---- out1 = attended @ Wo + bo + residual1 (into A) ----
    gemm_store(Wo, 128, Bx, A, sm + OFF_BO, A, Wsh, tid, t0, c0);
    __syncthreads();

    // ---- LayerNorm 2 (A -> Bx) ----
    layernorm(A, Bx, sm + OFF_G2, sm + OFF_BE2, tid);

    // ---- FFN ----
    ull acc2[4][4];
    #pragma unroll
    for (int j = 0; j < 4; ++j)
        #pragma unroll
        for (int i = 0; i < 4; ++i) acc2[j][i] = 0ull;

    #pragma unroll 1
    for (int j0 = 0; j0 < 512; j0 += 128) {
        ull h1[4][4];
        #pragma unroll
        for (int j = 0; j < 4; ++j)
            #pragma unroll
            for (int i = 0; i < 4; ++i) h1[j][i] = 0ull;

        gemm_acc(W1 + j0, 512, Bx, Wsh, h1, tid, t0, c0);

        const ull* bf = (const ull*)(sm + OFF_BF1 + j0 + c0);
        #pragma unroll
        for (int j = 0; j < 4; ++j) {
            float2* q = (float2*)(Qb + (t0 + j) * PAD + c0);
            #pragma unroll
            for (int i = 0; i < 4; ++i) {
                float2 f = unpk(add2(h1[j][i], bf[i]));
                q[i] = make_float2(fmaxf(f.x, 0.f), fmaxf(f.y, 0.f));
            }
        }
        gemm_acc(W2 + j0 * 128, 128, Qb, Wsh, acc2, tid, t0, c0);
    }

    const ull* bf2s = (const ull*)(sm + OFF_BF2 + c0);
    #pragma unroll
    for (int j = 0; j < 4; ++j) {
        ull* d = (ull*)(Bx + (t0 + j) * PAD + c0);
        const ull* r = (const ull*)(A + (t0 + j) * PAD + c0);
        #pragma unroll
        for (int i = 0; i < 4; ++i)
            d[i] = add2(add2(acc2[j][i], bf2s[i]), r[i]);
    }
    __syncthreads();

    // ---- coalesced global store ----
    float* og = out + (b * CC) * SS + s0;
    for (int idx = tid; idx < TOK * CC; idx += NTHREADS) {
        int c = idx >> 6;
        int t = idx & 63;
        og[c * SS + t] = Bx[t * PAD + c];
    }
}

extern "C" void kernel_launch(void* const* d_in, const int* in_sizes, int n_in,
                              void* d_out, int out_size)
{
    (void)in_sizes; (void)n_in; (void)out_size;
    cudaFuncSetAttribute(polar_attention_kernel,
                         cudaFuncAttributeMaxDynamicSharedMemorySize, SMEM_BYTES);

    const float* x     = (const float*)d_in[0];
    const float* polar = (const float*)d_in[1];
    const float* Wq    = (const float*)d_in[2];
    const float* bq    = (const float*)d_in[3];
    const float* Wk    = (const float*)d_in[4];
    const float* bk    = (const float*)d_in[5];
    const float* Wv    = (const float*)d_in[6];
    const float* bv    = (const float*)d_in[7];
    const float* Wp    = (const float*)d_in[8];
    const float* bp    = (const float*)d_in[9];
    const float* Wo    = (const float*)d_in[10];
    const float* bo    = (const float*)d_in[11];
    const float* g1    = (const float*)d_in[12];
    const float* be1   = (const float*)d_in[13];
    const float* g2    = (const float*)d_in[14];
    const float* be2   = (const float*)d_in[15];
    const float* W1    = (const float*)d_in[16];
    const float* bf1   = (const float*)d_in[17];
    const float* W2    = (const float*)d_in[18];
    const float* bf2   = (const float*)d_in[19];
    float* out = (float*)d_out;

    dim3 grid(NTOK / TOK);
    polar_attention_kernel<<<grid, NTHREADS, SMEM_BYTES>>>(
        x, polar, Wq, bq, Wk, bk, Wv, bv, Wp, bp, Wo, bo,
        g1, be1, g2, be2, W1, bf1, W2, bf2, out);
}

// round 4
// speedup vs baseline: 2.7976x; 2.4591x over previous
#include <cuda_runtime.h>

// Problem constants
#define CC   128
#define PCH  6
#define SS   131072
#define NB   2
#define NTOK (NB*SS)
#define TOK  64
#define PAD  132          // activation row stride: (lane/4)*4 + lane%4 -> conflict-free frags
#define NTHREADS 256
#define NHEAD 8
#define HDIM  16
#define WSTR 136          // weight staging row stride: (lane%4)*8 + lane/4 -> conflict-free
#define WBUF (32*WSTR)    // 4352 floats per stage buffer

// ---- shared memory layout (float offsets) ----
#define ROWF (TOK*PAD)                   // 8448
#define OFF_A    0                       // residual1 / out1        [64][132] fp32
#define OFF_B    (ROWF)                  // xn / attended / out2    [64][132]
#define OFF_Q    (2*ROWF)                // Q / relu(h) chunk
#define OFF_K    (3*ROWF)                // K
#define OFF_V    (4*ROWF)                // V
#define OFF_WSH  (5*ROWF)                // weight staging double buffer 2x(32x136)
#define OFF_WP   (OFF_WSH + 2*WBUF)
#define OFF_BQ   (OFF_WP  + 768)
#define OFF_BK   (OFF_BQ  + 128)
#define OFF_BV   (OFF_BK  + 128)
#define OFF_BP   (OFF_BV  + 128)
#define OFF_BO   (OFF_BP  + 128)
#define OFF_G1   (OFF_BO  + 128)
#define OFF_BE1  (OFF_G1  + 128)
#define OFF_G2   (OFF_BE1 + 128)
#define OFF_BE2  (OFF_G2  + 128)
#define OFF_BF2  (OFF_BE2 + 128)
#define OFF_BF1  (OFF_BF2 + 128)         // 512
#define OFF_POL  (OFF_BF1 + 512)         // polar [6][64]
#define SMEM_FLOATS (OFF_POL + 384)
#define SMEM_BYTES  (SMEM_FLOATS * 4)    // ~215.6 KB

// ---- tf32 / mma primitives ----
__device__ __forceinline__ unsigned tf32c(float f) {
    unsigned r; asm("cvt.rna.tf32.f32 %0, %1;" : "=r"(r) : "f"(f)); return r;
}
__device__ __forceinline__ void mma_tf32(float (&d)[4],
    unsigned a0, unsigned a1, unsigned a2, unsigned a3,
    unsigned b0, unsigned b1)
{
    asm("mma.sync.aligned.m16n8k8.row.col.f32.tf32.tf32.f32 "
        "{%0,%1,%2,%3}, {%4,%5,%6,%7}, {%8,%9}, {%0,%1,%2,%3};"
        : "+f"(d[0]), "+f"(d[1]), "+f"(d[2]), "+f"(d[3])
        : "r"(a0), "r"(a1), "r"(a2), "r"(a3), "r"(b0), "r"(b1));
}

// ---- cp.async staging (32 k-rows x 128 cols into stride-136 buffer) ----
#define CP_WAIT(N) asm volatile("cp.async.wait_group %0;" :: "n"(N) : "memory")

__device__ __forceinline__ void stage_copy(float* buf, const float* __restrict__ Wg,
                                           int ldW, int kk, int tid)
{
    #pragma unroll
    for (int it = 0; it < 4; ++it) {
        int flat = (tid + it * NTHREADS) * 4;
        int r = flat >> 7, c = flat & 127;
        unsigned dst = (unsigned)__cvta_generic_to_shared(buf + r * WSTR + c);
        const float* src = Wg + (kk + r) * ldW + c;
        asm volatile("cp.async.ca.shared.global [%0], [%1], 16;" :: "r"(dst), "l"(src) : "memory");
    }
    asm volatile("cp.async.commit_group;" ::: "memory");
}

// GEMM: acc[8 ntiles][4] += As[64x128](tf32 bits) @ W[128x128] (tf32 via cvt at load)
// Warp layout: m-warp = wid&3 (16 rows), n-warp = wid>>2 (64 cols = 8 n-tiles of 8)
__device__ __forceinline__ void gemm_mma(
    const float* __restrict__ Wg, int ldW,
    const float* __restrict__ As, float* __restrict__ Wsh,
    float (&acc)[8][4], int tid, bool skip_first_stage)
{
    const int lane = tid & 31;
    const int wid  = tid >> 5;
    const int m0 = (wid & 3) * 16;
    const int nb = (wid >> 2) * 64;
    const int qd = lane >> 2;
    const int tg = lane & 3;
    const float* aLo = As + (m0 + qd) * PAD + tg;
    const float* aHi = aLo + 8 * PAD;

    if (!skip_first_stage) stage_copy(Wsh, Wg, ldW, 0, tid);
    #pragma unroll
    for (int s = 0; s < 4; ++s) {
        if (s < 3) { stage_copy(Wsh + ((s + 1) & 1) * WBUF, Wg, ldW, (s + 1) * 32, tid); CP_WAIT(1); }
        else       { CP_WAIT(0); }
        __syncthreads();
        const float* wb = Wsh + (s & 1) * WBUF;
        #pragma unroll
        for (int ks = 0; ks < 4; ++ks) {
            const int kg = s * 32 + ks * 8;
            unsigned a0 = __float_as_uint(aLo[kg]);
            unsigned a2 = __float_as_uint(aLo[kg + 4]);
            unsigned a1 = __float_as_uint(aHi[kg]);
            unsigned a3 = __float_as_uint(aHi[kg + 4]);
            const float* b0p = wb + (ks * 8 + tg) * WSTR + nb + qd;
            const float* b1p = b0p + 4 * WSTR;
            #pragma unroll
            for (int nt = 0; nt < 8; ++nt) {
                unsigned b0 = tf32c(b0p[nt * 8]);
                unsigned b1 = tf32c(b1p[nt * 8]);
                mma_tf32(acc[nt], a0, a1, a2, a3, b0, b1);
            }
        }
        __syncthreads();
    }
}

// Epilogue: dst[m, n] = acc + bias (+res) (+relu) (+tf32 cvt)
__device__ __forceinline__ void epi_store(
    float (&acc)[8][4], float* __restrict__ dst,
    const float* __restrict__ bias, const float* __restrict__ res,
    bool do_relu, bool do_cvt, int tid)
{
    const int lane = tid & 31, wid = tid >> 5;
    const int m0 = (wid & 3) * 16, nb = (wid >> 2) * 64;
    const int r0 = m0 + (lane >> 2);
    const int tg = lane & 3;
    #pragma unroll
    for (int nt = 0; nt < 8; ++nt) {
        int cb = nb + nt * 8 + tg * 2;
        float2 b = *(const float2*)(bias + cb);
        float v0 = acc[nt][0] + b.x, v1 = acc[nt][1] + b.y;
        float v2 = acc[nt][2] + b.x, v3 = acc[nt][3] + b.y;
        if (res) {
            float2 rl = *(const float2*)(res + r0 * PAD + cb);
            float2 rh = *(const float2*)(res + (r0 + 8) * PAD + cb);
            v0 += rl.x; v1 += rl.y; v2 += rh.x; v3 += rh.y;
        }
        if (do_relu) {
            v0 = fmaxf(v0, 0.f); v1 = fmaxf(v1, 0.f);
            v2 = fmaxf(v2, 0.f); v3 = fmaxf(v3, 0.f);
        }
        if (do_cvt) {
            v0 = __uint_as_float(tf32c(v0)); v1 = __uint_as_float(tf32c(v1));
            v2 = __uint_as_float(tf32c(v2)); v3 = __uint_as_float(tf32c(v3));
        }
        *(float2*)(dst + r0 * PAD + cb)       = make_float2(v0, v1);
        *(float2*)(dst + (r0 + 8) * PAD + cb) = make_float2(v2, v3);
    }
}

// LayerNorm: 4 threads/token, shuffle reduction; optional tf32 output quantization
template<bool CVT>
__device__ __forceinline__ void layernorm(
    const float* __restrict__ A, float* __restrict__ Bx,
    const float* __restrict__ g, const float* __restrict__ be, int tid)
{
    int t = tid >> 2, q = tid & 3;
    const float4* rowA = (const float4*)(A + t * PAD + q * 32);
    float s = 0.f, sq = 0.f;
    float4 v[8];
    #pragma unroll
    for (int i = 0; i < 8; ++i) {
        v[i] = rowA[i];
        s  += v[i].x + v[i].y + v[i].z + v[i].w;
        sq += v[i].x * v[i].x + v[i].y * v[i].y + v[i].z * v[i].z + v[i].w * v[i].w;
    }
    s  += __shfl_xor_sync(0xffffffffu, s, 1);
    sq += __shfl_xor_sync(0xffffffffu, sq, 1);
    s  += __shfl_xor_sync(0xffffffffu, s, 2);
    sq += __shfl_xor_sync(0xffffffffu, sq, 2);
    float m = s * (1.f / CC);
    float rs = rsqrtf(sq * (1.f / CC) - m * m + 1e-5f);

    const float4* g4  = (const float4*)(g  + q * 32);
    const float4* be4 = (const float4*)(be + q * 32);
    float4* rowB = (float4*)(Bx + t * PAD + q * 32);
    #pragma unroll
    for (int i = 0; i < 8; ++i) {
        float4 gg = g4[i], bb = be4[i], o;
        o.x = (v[i].x - m) * rs * gg.x + bb.x;
        o.y = (v[i].y - m) * rs * gg.y + bb.y;
        o.z = (v[i].z - m) * rs * gg.z + bb.z;
        o.w = (v[i].w - m) * rs * gg.w + bb.w;
        if (CVT) {
            o.x = __uint_as_float(tf32c(o.x)); o.y = __uint_as_float(tf32c(o.y));
            o.z = __uint_as_float(tf32c(o.z)); o.w = __uint_as_float(tf32c(o.w));
        }
        rowB[i] = o;
    }
}

__global__ void __launch_bounds__(NTHREADS, 1)
polar_attention_kernel(
    const float* __restrict__ x,   const float* __restrict__ polar,
    const float* __restrict__ Wq,  const float* __restrict__ bq,
    const float* __restrict__ Wk,  const float* __restrict__ bk,
    const float* __restrict__ Wv,  const float* __restrict__ bv,
    const float* __restrict__ Wp,  const float* __restrict__ bp,
    const float* __restrict__ Wo,  const float* __restrict__ bo,
    const float* __restrict__ g1,  const float* __restrict__ be1,
    const float* __restrict__ g2,  const float* __restrict__ be2,
    const float* __restrict__ W1,  const float* __restrict__ bf1,
    const float* __restrict__ W2,  const float* __restrict__ bf2,
    float* __restrict__ out)
{
    extern __shared__ float sm[];
    float* A   = sm + OFF_A;
    float* Bx  = sm + OFF_B;
    float* Qb  = sm + OFF_Q;
    float* Kb  = sm + OFF_K;
    float* Vb  = sm + OFF_V;
    float* Wsh = sm + OFF_WSH;
    float* sWp = sm + OFF_WP;
    float* sPol= sm + OFF_POL;

    const int tid = threadIdx.x;
    const int n0  = blockIdx.x * TOK;
    const int b   = n0 / SS;
    const int s0  = n0 % SS;

    const float* xg = x + (b * CC) * SS + s0;

    // Prefetch first stage of Wq early (hidden under tile load + LN)
    stage_copy(Wsh, Wq, 128, 0, tid);

    // ---- stage small params ----
    for (int i = tid; i < 768; i += NTHREADS) sWp[i] = Wp[i];
    for (int i = tid; i < 512; i += NTHREADS) sm[OFF_BF1 + i] = bf1[i];
    if (tid < 128) {
        sm[OFF_BQ  + tid] = bq[tid];
        sm[OFF_BK  + tid] = bk[tid];
        sm[OFF_BV  + tid] = bv[tid];
        sm[OFF_BP  + tid] = bp[tid];
        sm[OFF_BO  + tid] = bo[tid];
        sm[OFF_G1  + tid] = g1[tid];
        sm[OFF_BE1 + tid] = be1[tid];
        sm[OFF_G2  + tid] = g2[tid];
        sm[OFF_BE2 + tid] = be2[tid];
        sm[OFF_BF2 + tid] = bf2[tid];
    }

    // ---- load x tile (coalesced) ----
    for (int idx = tid; idx < TOK * CC; idx += NTHREADS) {
        int c = idx >> 6;
        int t = idx & 63;
        A[t * PAD + c] = xg[c * SS + t];
    }
    for (int i = tid; i < PCH * TOK; i += NTHREADS) {
        int p = i >> 6;
        int t = i & 63;
        sPol[p * 64 + t] = polar[(b * PCH + p) * SS + s0 + t];
    }
    __syncthreads();

    // ---- x_with_polar = x + polar @ Wp + bp (into A) ----
    for (int idx = tid; idx < TOK * 32; idx += NTHREADS) {
        int t = idx >> 5;
        int c4 = (idx & 31) * 4;
        float4 v = *(const float4*)(A + t * PAD + c4);
        #pragma unroll
        for (int p = 0; p < PCH; ++p) {
            float pv = sPol[p * 64 + t];
            float4 w = *(const float4*)(sWp + p * 128 + c4);
            v.x = fmaf(pv, w.x, v.x); v.y = fmaf(pv, w.y, v.y);
            v.z = fmaf(pv, w.z, v.z); v.w = fmaf(pv, w.w, v.w);
        }
        float4 bb = *(const float4*)(sm + OFF_BP + c4);
        v.x += bb.x; v.y += bb.y; v.z += bb.z; v.w += bb.w;
        *(float4*)(A + t * PAD + c4) = v;
    }
    __syncthreads();

    // ---- LayerNorm 1 (A -> Bx, tf32-quantized: only feeds QKV GEMMs) ----
    layernorm<true>(A, Bx, sm + OFF_G1, sm + OFF_BE1, tid);

    // ---- Q,K,V GEMMs (tensor core) ----
    {
        float acc[8][4];
        #pragma unroll
        for (int i = 0; i < 8; ++i) { acc[i][0]=acc[i][1]=acc[i][2]=acc[i][3]=0.f; }
        gemm_mma(Wq, 128, Bx, Wsh, acc, tid, true);    // first stage already prefetched
        epi_store(acc, Qb, sm + OFF_BQ, nullptr, false, false, tid);
    }
    {
        float acc[8][4];
        #pragma unroll
        for (int i = 0; i < 8; ++i) { acc[i][0]=acc[i][1]=acc[i][2]=acc[i][3]=0.f; }
        gemm_mma(Wk, 128, Bx, Wsh, acc, tid, false);
        epi_store(acc, Kb, sm + OFF_BK, nullptr, false, false, tid);
    }
    {
        float acc[8][4];
        #pragma unroll
        for (int i = 0; i < 8; ++i) { acc[i][0]=acc[i][1]=acc[i][2]=acc[i][3]=0.f; }
        gemm_mma(Wv, 128, Bx, Wsh, acc, tid, false);
        epi_store(acc, Vb, sm + OFF_BV, nullptr, false, false, tid);
    }
    __syncthreads();

    // ---- per-token cross-head attention: 4 threads/token, 2 heads each -> Bx (tf32) ----
    {
        const int t  = tid >> 2;
        const int h0 = (tid & 3) * 2;
        const float* Qr = Qb + t * PAD;
        const float* Kr = Kb + t * PAD;
        const float* Vr = Vb + t * PAD;
        float sc[2][NHEAD];
        const float scale = 0.25f;
        #pragma unroll
        for (int hh = 0; hh < 2; ++hh) {
            float q[HDIM];
            #pragma unroll
            for (int d = 0; d < HDIM; ++d) q[d] = Qr[(h0 + hh) * HDIM + d];
            #pragma unroll
            for (int g = 0; g < NHEAD; ++g) {
                float s = 0.f;
                #pragma unroll
                for (int d = 0; d < HDIM; ++d)
                    s = fmaf(q[d], Kr[g * HDIM + d], s);
                sc[hh][g] = s * scale;
            }
            float mx = sc[hh][0];
            #pragma unroll
            for (int g = 1; g < NHEAD; ++g) mx = fmaxf(mx, sc[hh][g]);
            float sum = 0.f;
            #pragma unroll
            for (int g = 0; g < NHEAD; ++g) {
                float e = __expf(sc[hh][g] - mx);
                sc[hh][g] = e; sum += e;
            }
            float inv = 1.f / sum;
            #pragma unroll
            for (int g = 0; g < NHEAD; ++g) sc[hh][g] *= inv;
        }
        #pragma unroll
        for (int hh = 0; hh < 2; ++hh)
            #pragma unroll
            for (int d = 0; d < HDIM; ++d) {
                float a = 0.f;
                #pragma unroll
                for (int g = 0; g < NHEAD; ++g)
                    a = fmaf(sc[hh][g], Vr[g * HDIM + d], a);
                Bx[t * PAD + (h0 + hh) * HDIM + d] = __uint_as_float(tf32c(a));
            }
    }
    __syncthreads();

    // ---- out1 = attended @ Wo + bo + residual1 (into A, fp32) ----
    {
        float acc[8][4];
        #pragma unroll
        for (int i = 0; i < 8; ++i) { acc[i][0]=acc[i][1]=acc[i][2]=acc[i][3]=0.f; }
        gemm_mma(Wo, 128, Bx, Wsh, acc, tid, false);
        epi_store(acc, A, sm + OFF_BO, A, false, false, tid);
    }
    __syncthreads();

    // ---- LayerNorm 2 (A -> Bx, tf32: only feeds FFN1) ----
    layernorm<true>(A, Bx, sm + OFF_G2, sm + OFF_BE2, tid);

    // ---- FFN: out2 = relu(xn2 @ W1 + bf1) @ W2 + bf2 + out1 ----
    float acc2[8][4];
    #pragma unroll
    for (int i = 0; i < 8; ++i) { acc2[i][0]=acc2[i][1]=acc2[i][2]=acc2[i][3]=0.f; }

    #pragma unroll 1
    for (int j0 = 0; j0 < 512; j0 += 128) {
        float h1[8][4];
        #pragma unroll
        for (int i = 0; i < 8; ++i) { h1[i][0]=h1[i][1]=h1[i][2]=h1[i][3]=0.f; }
        gemm_mma(W1 + j0, 512, Bx, Wsh, h1, tid, false);
        epi_store(h1, Qb, sm + OFF_BF1 + j0, nullptr, true, true, tid);  // relu + tf32
        gemm_mma(W2 + j0 * 128, 128, Qb, Wsh, acc2, tid, false);
    }
    epi_store(acc2, Bx, sm + OFF_BF2, A, false, false, tid);
    __syncthreads();

    // ---- coalesced global store ----
    float* og = out + (b * CC) * SS + s0;
    for (int idx = tid; idx < TOK * CC; idx += NTHREADS) {
        int c = idx >> 6;
        int t = idx & 63;
        og[c * SS + t] = Bx[t * PAD + c];
    }
}

extern "C" void kernel_launch(void* const* d_in, const int* in_sizes, int n_in,
                              void* d_out, int out_size)
{
    (void)in_sizes; (void)n_in; (void)out_size;
    cudaFuncSetAttribute(polar_attention_kernel,
                         cudaFuncAttributeMaxDynamicSharedMemorySize, SMEM_BYTES);

    const float* x     = (const float*)d_in[0];
    const float* polar = (const float*)d_in[1];
    const float* Wq    = (const float*)d_in[2];
    const float* bq    = (const float*)d_in[3];
    const float* Wk    = (const float*)d_in[4];
    const float* bk    = (const float*)d_in[5];
    const float* Wv    = (const float*)d_in[6];
    const float* bv    = (const float*)d_in[7];
    const float* Wp    = (const float*)d_in[8];
    const float* bp    = (const float*)d_in[9];
    const float* Wo    = (const float*)d_in[10];
    const float* bo    = (const float*)d_in[11];
    const float* g1    = (const float*)d_in[12];
    const float* be1   = (const float*)d_in[13];
    const float* g2    = (const float*)d_in[14];
    const float* be2   = (const float*)d_in[15];
    const float* W1    = (const float*)d_in[16];
    const float* bf1   = (const float*)d_in[17];
    const float* W2    = (const float*)d_in[18];
    const float* bf2   = (const float*)d_in[19];
    float* out = (float*)d_out;

    dim3 grid(NTOK / TOK);
    polar_attention_kernel<<<grid, NTHREADS, SMEM_BYTES>>>(
        x, polar, Wq, bq, Wk, bk, Wv, bv, Wp, bp, Wo, bo,
        g1, be1, g2, be2, W1, bf1, W2, bf2, out);
}

// round 5
// speedup vs baseline: 6.0151x; 2.1501x over previous
#include <cuda_runtime.h>
#include <cuda_fp16.h>

// Problem constants
#define CC   128
#define PCH  6
#define SS   131072
#define NTOK 262144
#define TOK  64
#define NTHREADS 256
#define NHEAD 8
#define HDIM  16

#define PADA 132        // fp32 residual buffer stride (floats)
#define STRA 68         // fp16 activation stride (32-bit words): 68%32=4 -> frag banks qd*4+tg
#define WSTG 136        // staged weight stride (words): 136%32=8 -> frag banks tg*8+qd

// ---- shared memory layout (32-bit word offsets) ----
#define OFF_A    0                       // fp32 residual/out        [64][132]  8448
#define OFF_X    8448                    // fp16 GEMM input buf      [64][68]
#define OFF_Q    (OFF_X + 64*STRA)       // 12800  Q / relu-chunk? (Q)
#define OFF_K    (OFF_Q + 64*STRA)       // 17152  K / relu-chunk
#define OFF_V    (OFF_K + 64*STRA)       // 21504  V
#define OFF_WS   (OFF_V + 64*STRA)       // 25856  staged weights [16][136]
#define OFF_POL  (OFF_WS + 16*WSTG)      // 28032  polar [6][64]
#define SMEM_WORDS (OFF_POL + PCH*64)    // 28416
#define SMEM_BYTES (SMEM_WORDS*4)        // 113664 B -> 2 CTAs/SM

// ---- fp16 pack/unpack ----
__device__ __forceinline__ unsigned pk(float lo, float hi) {
    __half2 h = __floats2half2_rn(lo, hi);
    return *reinterpret_cast<unsigned*>(&h);
}
__device__ __forceinline__ float2 up(unsigned w) {
    __half2 h = *reinterpret_cast<__half2*>(&w);
    return __half22float2(h);
}

// ---- mma m16n8k16 fp16 in, fp32 accum ----
__device__ __forceinline__ void mma16(float (&d)[4],
    unsigned a0, unsigned a1, unsigned a2, unsigned a3, unsigned b0, unsigned b1)
{
    asm("mma.sync.aligned.m16n8k16.row.col.f32.f16.f16.f32 "
        "{%0,%1,%2,%3}, {%4,%5,%6,%7}, {%8,%9}, {%0,%1,%2,%3};"
        : "+f"(d[0]), "+f"(d[1]), "+f"(d[2]), "+f"(d[3])
        : "r"(a0), "r"(a1), "r"(a2), "r"(a3), "r"(b0), "r"(b1));
}

// staged-weight STS: unit u covers k-pair row w=u>>5, cols c4..c4+3 of 32kx128n stage
__device__ __forceinline__ void sts_unit(unsigned* ws, int u, float4 a, float4 b) {
    int w = u >> 5, c4 = (u & 31) << 2;
    uint4 p;
    p.x = pk(a.x, b.x); p.y = pk(a.y, b.y);
    p.z = pk(a.z, b.z); p.w = pk(a.w, b.w);
    *reinterpret_cast<uint4*>(ws + w * WSTG + c4) = p;
}

// GEMM: acc[8][4] += X16[64x128 fp16] @ W[128x128 fp32->fp16]
// warps: m = (wid&3)*16, n = (wid>>2)*64 (8 n-tiles of 8)
__device__ __forceinline__ void gemm16(
    const float* __restrict__ Wg, int ldW,
    const unsigned* __restrict__ Xs, unsigned* __restrict__ ws,
    float (&acc)[8][4], int tid)
{
    const int lane = tid & 31, wid = tid >> 5;
    const int m0 = (wid & 3) << 4, nb = (wid >> 2) << 6;
    const int qd = lane >> 2, tg = lane & 3;
    const unsigned* aR = Xs + (m0 + qd) * STRA;

    const int w0 = tid >> 5;            // unit0 k-pair row (0..7)
    const int c4 = (tid & 31) << 2;
    const int w1 = w0 + 8;              // unit1 (tid+256)

    float4 p0a, p0b, p1a, p1b;
    {
        const float* g0 = Wg + 2 * w0 * ldW + c4;
        const float* g1 = Wg + 2 * w1 * ldW + c4;
        p0a = *(const float4*)g0;          p0b = *(const float4*)(g0 + ldW);
        p1a = *(const float4*)g1;          p1b = *(const float4*)(g1 + ldW);
    }
    sts_unit(ws, tid, p0a, p0b);
    sts_unit(ws, tid + 256, p1a, p1b);
    __syncthreads();

    #pragma unroll
    for (int s = 0; s < 4; ++s) {
        if (s < 3) {  // prefetch next stage into regs (hidden under MMAs)
            const float* gb = Wg + (s + 1) * 32 * ldW;
            const float* g0 = gb + 2 * w0 * ldW + c4;
            const float* g1 = gb + 2 * w1 * ldW + c4;
            p0a = *(const float4*)g0;      p0b = *(const float4*)(g0 + ldW);
            p1a = *(const float4*)g1;      p1b = *(const float4*)(g1 + ldW);
        }
        #pragma unroll
        for (int ks = 0; ks < 2; ++ks) {
            const int g = s * 2 + ks;
            unsigned a0 = aR[g * 8 + tg];
            unsigned a2 = aR[g * 8 + tg + 4];
            unsigned a1 = aR[8 * STRA + g * 8 + tg];
            unsigned a3 = aR[8 * STRA + g * 8 + tg + 4];
            const unsigned* b0p = ws + (ks * 8 + tg) * WSTG + nb + qd;
            const unsigned* b1p = b0p + 4 * WSTG;
            #pragma unroll
            for (int nt = 0; nt < 8; ++nt)
                mma16(acc[nt], a0, a1, a2, a3, b0p[nt * 8], b1p[nt * 8]);
        }
        __syncthreads();
        if (s < 3) {
            sts_unit(ws, tid, p0a, p0b);
            sts_unit(ws, tid + 256, p1a, p1b);
            __syncthreads();
        }
    }
}

// epilogue -> packed fp16 buffer (+bias, optional relu)
__device__ __forceinline__ void epi16(float (&acc)[8][4], unsigned* __restrict__ dst,
                                      const float* __restrict__ bias, bool relu, int tid)
{
    const int lane = tid & 31, wid = tid >> 5;
    const int m0 = (wid & 3) << 4, nb = (wid >> 2) << 6;
    const int r0 = m0 + (lane >> 2), tg = lane & 3;
    #pragma unroll
    for (int nt = 0; nt < 8; ++nt) {
        int cb = nb + nt * 8 + tg * 2;
        float2 b = *(const float2*)(bias + cb);
        float v0 = acc[nt][0] + b.x, v1 = acc[nt][1] + b.y;
        float v2 = acc[nt][2] + b.x, v3 = acc[nt][3] + b.y;
        if (relu) {
            v0 = fmaxf(v0, 0.f); v1 = fmaxf(v1, 0.f);
            v2 = fmaxf(v2, 0.f); v3 = fmaxf(v3, 0.f);
        }
        dst[r0 * STRA + (cb >> 1)]       = pk(v0, v1);
        dst[(r0 + 8) * STRA + (cb >> 1)] = pk(v2, v3);
    }
}

// epilogue -> fp32 A in place: A = acc + bias + A (residual)
__device__ __forceinline__ void epi32_inplace(float (&acc)[8][4], float* __restrict__ A,
                                              const float* __restrict__ bias, int tid)
{
    const int lane = tid & 31, wid = tid >> 5;
    const int m0 = (wid & 3) << 4, nb = (wid >> 2) << 6;
    const int r0 = m0 + (lane >> 2), tg = lane & 3;
    #pragma unroll
    for (int nt = 0; nt < 8; ++nt) {
        int cb = nb + nt * 8 + tg * 2;
        float2 b = *(const float2*)(bias + cb);
        float2 rl = *(const float2*)(A + r0 * PADA + cb);
        float2 rh = *(const float2*)(A + (r0 + 8) * PADA + cb);
        *(float2*)(A + r0 * PADA + cb)       = make_float2(acc[nt][0] + b.x + rl.x, acc[nt][1] + b.y + rl.y);
        *(float2*)(A + (r0 + 8) * PADA + cb) = make_float2(acc[nt][2] + b.x + rh.x, acc[nt][3] + b.y + rh.y);
    }
}

// LayerNorm: A fp32 -> X fp16 packed. 4 threads/token, shuffle reduce.
__device__ __forceinline__ void ln16(const float* __restrict__ A, unsigned* __restrict__ X,
                                     const float* __restrict__ g, const float* __restrict__ be, int tid)
{
    int t = tid >> 2, q = tid & 3;
    const float4* rowA = (const float4*)(A + t * PADA + q * 32);
    float s = 0.f, sq = 0.f;
    float4 v[8];
    #pragma unroll
    for (int i = 0; i < 8; ++i) {
        v[i] = rowA[i];
        s  += v[i].x + v[i].y + v[i].z + v[i].w;
        sq += v[i].x * v[i].x + v[i].y * v[i].y + v[i].z * v[i].z + v[i].w * v[i].w;
    }
    s  += __shfl_xor_sync(0xffffffffu, s, 1);
    sq += __shfl_xor_sync(0xffffffffu, sq, 1);
    s  += __shfl_xor_sync(0xffffffffu, s, 2);
    sq += __shfl_xor_sync(0xffffffffu, sq, 2);
    float m = s * (1.f / CC);
    float rs = rsqrtf(sq * (1.f / CC) - m * m + 1e-5f);

    const float4* g4  = (const float4*)(g  + q * 32);
    const float4* be4 = (const float4*)(be + q * 32);
    unsigned* o = X + t * STRA + q * 16;
    #pragma unroll
    for (int i = 0; i < 8; ++i) {
        float4 gg = g4[i], bb = be4[i];
        float ox = (v[i].x - m) * rs * gg.x + bb.x;
        float oy = (v[i].y - m) * rs * gg.y + bb.y;
        float oz = (v[i].z - m) * rs * gg.z + bb.z;
        float ow = (v[i].w - m) * rs * gg.w + bb.w;
        o[i * 2]     = pk(ox, oy);
        o[i * 2 + 1] = pk(oz, ow);
    }
}

#define ZERO_ACC(a) { _Pragma("unroll") for (int _i = 0; _i < 8; ++_i) { a[_i][0]=0.f; a[_i][1]=0.f; a[_i][2]=0.f; a[_i][3]=0.f; } }

__global__ void __launch_bounds__(NTHREADS, 2)
polar_attention_kernel(
    const float* __restrict__ x,   const float* __restrict__ polar,
    const float* __restrict__ Wq,  const float* __restrict__ bq,
    const float* __restrict__ Wk,  const float* __restrict__ bk,
    const float* __restrict__ Wv,  const float* __restrict__ bv,
    const float* __restrict__ Wp,  const float* __restrict__ bp,
    const float* __restrict__ Wo,  const float* __restrict__ bo,
    const float* __restrict__ g1,  const float* __restrict__ be1,
    const float* __restrict__ g2,  const float* __restrict__ be2,
    const float* __restrict__ W1,  const float* __restrict__ bf1,
    const float* __restrict__ W2,  const float* __restrict__ bf2,
    float* __restrict__ out)
{
    extern __shared__ float sm[];
    unsigned* smu = (unsigned*)sm;
    float*    A   = sm + OFF_A;
    unsigned* X16 = smu + OFF_X;
    unsigned* Q16 = smu + OFF_Q;
    unsigned* K16 = smu + OFF_K;
    unsigned* V16 = smu + OFF_V;
    unsigned* WS  = smu + OFF_WS;
    float*    pol = sm + OFF_POL;

    const int tid = threadIdx.x;
    const int n0  = blockIdx.x * TOK;
    const int b   = n0 / SS;
    const int s0  = n0 % SS;

    const float* xg = x + (b * CC) * SS + s0;

    // ---- load x tile + polar tile (coalesced) ----
    for (int idx = tid; idx < TOK * CC; idx += NTHREADS) {
        int c = idx >> 6, t = idx & 63;
        A[t * PADA + c] = xg[c * SS + t];
    }
    for (int i = tid; i < PCH * TOK; i += NTHREADS) {
        int p = i >> 6, t = i & 63;
        pol[p * 64 + t] = polar[(b * PCH + p) * SS + s0 + t];
    }
    __syncthreads();

    // ---- x_with_polar = x + polar @ Wp + bp (into A); Wp/bp from gmem ----
    for (int idx = tid; idx < TOK * 32; idx += NTHREADS) {
        int t = idx >> 5, c4 = (idx & 31) * 4;
        float4 v = *(const float4*)(A + t * PADA + c4);
        #pragma unroll
        for (int p = 0; p < PCH; ++p) {
            float pv = pol[p * 64 + t];
            float4 w = *(const float4*)(Wp + p * 128 + c4);
            v.x = fmaf(pv, w.x, v.x); v.y = fmaf(pv, w.y, v.y);
            v.z = fmaf(pv, w.z, v.z); v.w = fmaf(pv, w.w, v.w);
        }
        float4 bb = *(const float4*)(bp + c4);
        v.x += bb.x; v.y += bb.y; v.z += bb.z; v.w += bb.w;
        *(float4*)(A + t * PADA + c4) = v;
    }
    __syncthreads();

    // ---- LN1 -> X16 ----
    ln16(A, X16, g1, be1, tid);
    // (visibility of X16 ensured by gemm16's internal prologue sync)

    float acc[8][4];
    ZERO_ACC(acc); gemm16(Wq, 128, X16, WS, acc, tid); epi16(acc, Q16, bq, false, tid);
    ZERO_ACC(acc); gemm16(Wk, 128, X16, WS, acc, tid); epi16(acc, K16, bk, false, tid);
    ZERO_ACC(acc); gemm16(Wv, 128, X16, WS, acc, tid); epi16(acc, V16, bv, false, tid);
    __syncthreads();

    // ---- per-token cross-head attention: 4 thr/token, 2 heads each -> X16 ----
    {
        const int t = tid >> 2;
        const int h0q = (tid & 3) * 2;
        const unsigned* Qr = Q16 + t * STRA;
        const unsigned* Kr = K16 + t * STRA;
        const unsigned* Vr = V16 + t * STRA;
        #pragma unroll
        for (int hh = 0; hh < 2; ++hh) {
            const int h = h0q + hh;
            float q[16];
            #pragma unroll
            for (int i = 0; i < 8; ++i) {
                float2 f = up(Qr[h * 8 + i]);
                q[2 * i] = f.x; q[2 * i + 1] = f.y;
            }
            float sc[NHEAD];
            #pragma unroll
            for (int g = 0; g < NHEAD; ++g) {
                float s = 0.f;
                #pragma unroll
                for (int i = 0; i < 8; ++i) {
                    float2 f = up(Kr[g * 8 + i]);
                    s = fmaf(q[2 * i], f.x, s);
                    s = fmaf(q[2 * i + 1], f.y, s);
                }
                sc[g] = s * 0.25f;
            }
            float mx = sc[0];
            #pragma unroll
            for (int g = 1; g < NHEAD; ++g) mx = fmaxf(mx, sc[g]);
            float sum = 0.f;
            #pragma unroll
            for (int g = 0; g < NHEAD; ++g) { float e = __expf(sc[g] - mx); sc[g] = e; sum += e; }
            float inv = 1.f / sum;
            #pragma unroll
            for (int g = 0; g < NHEAD; ++g) sc[g] *= inv;

            float att[16];
            #pragma unroll
            for (int i = 0; i < 16; ++i) att[i] = 0.f;
            #pragma unroll
            for (int g = 0; g < NHEAD; ++g) {
                float w = sc[g];
                #pragma unroll
                for (int i = 0; i < 8; ++i) {
                    float2 f = up(Vr[g * 8 + i]);
                    att[2 * i]     = fmaf(w, f.x, att[2 * i]);
                    att[2 * i + 1] = fmaf(w, f.y, att[2 * i + 1]);
                }
            }
            #pragma unroll
            for (int i = 0; i < 8; ++i)
                X16[t * STRA + h * 8 + i] = pk(att[2 * i], att[2 * i + 1]);
        }
    }
    __syncthreads();

    // ---- out1 = attended @ Wo + bo + residual1 (A in place) ----
    ZERO_ACC(acc); gemm16(Wo, 128, X16, WS, acc, tid); epi32_inplace(acc, A, bo, tid);
    __syncthreads();

    // ---- LN2 -> X16 ----
    ln16(A, X16, g2, be2, tid);

    // ---- FFN: out2 = relu(xn2 @ W1 + bf1) @ W2 + bf2 + out1 ----
    float acc2[8][4];
    ZERO_ACC(acc2);
    #pragma unroll 1
    for (int j0 = 0; j0 < 512; j0 += 128) {
        float h1[8][4];
        ZERO_ACC(h1);
        gemm16(W1 + j0, 512, X16, WS, h1, tid);
        epi16(h1, K16, bf1 + j0, true, tid);       // relu chunk -> K16 (dead after attention)
        gemm16(W2 + j0 * 128, 128, K16, WS, acc2, tid);
    }
    epi32_inplace(acc2, A, bf2, tid);              // out2 -> A
    __syncthreads();

    // ---- coalesced global store ----
    float* og = out + (b * CC) * SS + s0;
    for (int idx = tid; idx < TOK * CC; idx += NTHREADS) {
        int c = idx >> 6, t = idx & 63;
        og[c * SS + t] = A[t * PADA + c];
    }
}

extern "C" void kernel_launch(void* const* d_in, const int* in_sizes, int n_in,
                              void* d_out, int out_size)
{
    (void)in_sizes; (void)n_in; (void)out_size;
    cudaFuncSetAttribute(polar_attention_kernel,
                         cudaFuncAttributeMaxDynamicSharedMemorySize, SMEM_BYTES);

    const float* x     = (const float*)d_in[0];
    const float* polar = (const float*)d_in[1];
    const float* Wq    = (const float*)d_in[2];
    const float* bq    = (const float*)d_in[3];
    const float* Wk    = (const float*)d_in[4];
    const float* bk    = (const float*)d_in[5];
    const float* Wv    = (const float*)d_in[6];
    const float* bv    = (const float*)d_in[7];
    const float* Wp    = (const float*)d_in[8];
    const float* bp    = (const float*)d_in[9];
    const float* Wo    = (const float*)d_in[10];
    const float* bo    = (const float*)d_in[11];
    const float* g1    = (const float*)d_in[12];
    const float* be1   = (const float*)d_in[13];
    const float* g2    = (const float*)d_in[14];
    const float* be2   = (const float*)d_in[15];
    const float* W1    = (const float*)d_in[16];
    const float* bf1   = (const float*)d_in[17];
    const float* W2    = (const float*)d_in[18];
    const float* bf2   = (const float*)d_in[19];
    float* out = (float*)d_out;

    dim3 grid(NTOK / TOK);
    polar_attention_kernel<<<grid, NTHREADS, SMEM_BYTES>>>(
        x, polar, Wq, bq, Wk, bk, Wv, bv, Wp, bp, Wo, bo,
        g1, be1, g2, be2, W1, bf1, W2, bf2, out);
}

// round 6
// speedup vs baseline: 8.6404x; 1.4365x over previous
#include <cuda_runtime.h>
#include <cuda_fp16.h>

#define CC   128
#define PCH  6
#define SS   131072
#define NTOK 262144
#define TOK  64
#define NTHREADS 256
#define NHEAD 8

#define STRA 68      // fp16 activation row stride (u32 words), [64 tokens][64 word cols + pad]
#define ASTR 68      // fp32 residual A column stride: A[c][t], 64 tokens + pad

// ---- shared memory layout (32-bit word offsets) ----
#define OFF_A    0                       // fp32 A [128][68] col-major  = 8704
#define OFF_X    (128*ASTR)              // fp16 X  [64][68]
#define OFF_Q    (OFF_X + 64*STRA)
#define OFF_K    (OFF_Q + 64*STRA)
#define OFF_V    (OFF_K + 64*STRA)
#define OFF_POL  (OFF_V + 64*STRA)       // polar [6][64]
#define SMEM_WORDS (OFF_POL + PCH*64)    // 26496
#define SMEM_BYTES (SMEM_WORDS*4)        // 105984 B -> 2 CTAs/SM

// 12 fragment blocks of 128x128: Wq,Wk,Wv,Wo, W1 n-chunks x4, W2 k-chunks x4
__device__ unsigned g_wfrag[12 * 8192];

// ---- fp16 helpers ----
__device__ __forceinline__ unsigned pk(float lo, float hi) {
    __half2 h = __floats2half2_rn(lo, hi);
    return *reinterpret_cast<unsigned*>(&h);
}
__device__ __forceinline__ float2 up(unsigned w) {
    __half2 h = *reinterpret_cast<__half2*>(&w);
    return __half22float2(h);
}
__device__ __forceinline__ void mma16(float (&d)[4],
    unsigned a0, unsigned a1, unsigned a2, unsigned a3, unsigned b0, unsigned b1)
{
    asm("mma.sync.aligned.m16n8k16.row.col.f32.f16.f16.f32 "
        "{%0,%1,%2,%3}, {%4,%5,%6,%7}, {%8,%9}, {%0,%1,%2,%3};"
        : "+f"(d[0]), "+f"(d[1]), "+f"(d[2]), "+f"(d[3])
        : "r"(a0), "r"(a1), "r"(a2), "r"(a3), "r"(b0), "r"(b1));
}

// ---- weight conversion kernel: fp32 row-major -> fp16 fragment-major ----
// word w within block: w = (((ks*4 + nw)*2 + h)*32 + lane)*4 + q4
//   j = q4&1 (b0/b1 -> k or k+8), ntl = q4>>1, nt = h*2 + ntl
//   k = k0 + ks*16 + tg*2 + j*8 ; n = n0 + nw*32 + nt*8 + qd
__global__ void convert_weights(const float* __restrict__ Wq, const float* __restrict__ Wk,
                                const float* __restrict__ Wv, const float* __restrict__ Wo,
                                const float* __restrict__ W1, const float* __restrict__ W2)
{
    int gid = blockIdx.x * blockDim.x + threadIdx.x;
    int blk = gid >> 13;
    int w   = gid & 8191;
    int q4   = w & 3;
    int lane = (w >> 2) & 31;
    int h    = (w >> 7) & 1;
    int nw   = (w >> 8) & 3;
    int ks   = w >> 10;
    int j    = q4 & 1;
    int nt   = h * 2 + (q4 >> 1);
    int qd = lane >> 2, tg = lane & 3;
    int k = ks * 16 + tg * 2 + j * 8;
    int n = nw * 32 + nt * 8 + qd;

    const float* W; int ld = 128, k0 = 0, n0 = 0;
    if      (blk == 0) W = Wq;
    else if (blk == 1) W = Wk;
    else if (blk == 2) W = Wv;
    else if (blk == 3) W = Wo;
    else if (blk < 8)  { W = W1; ld = 512; n0 = (blk - 4) * 128; }
    else               { W = W2; k0 = (blk - 8) * 128; }

    const float* p = W + (size_t)(k0 + k) * ld + n0 + n;
    g_wfrag[gid] = pk(p[0], p[ld]);
}

// ---- GEMM: acc[2 mtiles][4 ntiles][4] += X[64x128 fp16] @ Wfrag ----
// warps: mw = wid&1 (32 rows), nw = wid>>1 (32 cols)
__device__ __forceinline__ void gemm_f(
    const unsigned* __restrict__ Wf,
    const unsigned* __restrict__ Xs,
    float (&acc)[2][4][4], int tid)
{
    const int lane = tid & 31, wid = tid >> 5;
    const int mw = wid & 1, nw = wid >> 1;
    const int qd = lane >> 2, tg = lane & 3;
    const unsigned* aB = Xs + (mw * 32 + qd) * STRA + tg;
    const uint4* bp = (const uint4*)Wf + nw * 64 + lane;

    uint4 B0 = bp[0], B1 = bp[32];
    #pragma unroll
    for (int ks = 0; ks < 8; ++ks) {
        uint4 nB0 = B0, nB1 = B1;
        if (ks < 7) { nB0 = bp[(ks + 1) * 256]; nB1 = bp[(ks + 1) * 256 + 32]; }
        unsigned a[2][4];
        #pragma unroll
        for (int mm = 0; mm < 2; ++mm) {
            const unsigned* ar = aB + mm * (16 * STRA) + ks * 8;
            a[mm][0] = ar[0];
            a[mm][1] = ar[8 * STRA];
            a[mm][2] = ar[4];
            a[mm][3] = ar[8 * STRA + 4];
        }
        #pragma unroll
        for (int mm = 0; mm < 2; ++mm) {
            mma16(acc[mm][0], a[mm][0], a[mm][1], a[mm][2], a[mm][3], B0.x, B0.y);
            mma16(acc[mm][1], a[mm][0], a[mm][1], a[mm][2], a[mm][3], B0.z, B0.w);
            mma16(acc[mm][2], a[mm][0], a[mm][1], a[mm][2], a[mm][3], B1.x, B1.y);
            mma16(acc[mm][3], a[mm][0], a[mm][1], a[mm][2], a[mm][3], B1.z, B1.w);
        }
        B0 = nB0; B1 = nB1;
    }
}

// epilogue -> fp16 activation buffer (+bias from gmem, optional relu)
__device__ __forceinline__ void epi16(float (&acc)[2][4][4], unsigned* __restrict__ dst,
                                      const float* __restrict__ bias, bool relu, int tid)
{
    const int lane = tid & 31, wid = tid >> 5;
    const int mw = wid & 1, nw = wid >> 1;
    const int qd = lane >> 2, tg = lane & 3;
    #pragma unroll
    for (int nt = 0; nt < 4; ++nt) {
        const int cb = nw * 32 + nt * 8 + tg * 2;
        float2 b = *(const float2*)(bias + cb);
        #pragma unroll
        for (int mm = 0; mm < 2; ++mm) {
            const int r0 = mw * 32 + mm * 16 + qd;
            float v0 = acc[mm][nt][0] + b.x, v1 = acc[mm][nt][1] + b.y;
            float v2 = acc[mm][nt][2] + b.x, v3 = acc[mm][nt][3] + b.y;
            if (relu) {
                v0 = fmaxf(v0, 0.f); v1 = fmaxf(v1, 0.f);
                v2 = fmaxf(v2, 0.f); v3 = fmaxf(v3, 0.f);
            }
            dst[r0 * STRA + (cb >> 1)]       = pk(v0, v1);
            dst[(r0 + 8) * STRA + (cb >> 1)] = pk(v2, v3);
        }
    }
}

// epilogue -> fp32 A (col-major) in place: A[c][t] += acc + bias
__device__ __forceinline__ void epi32A(float (&acc)[2][4][4], float* __restrict__ A,
                                       const float* __restrict__ bias, int tid)
{
    const int lane = tid & 31, wid = tid >> 5;
    const int mw = wid & 1, nw = wid >> 1;
    const int qd = lane >> 2, tg = lane & 3;
    #pragma unroll
    for (int nt = 0; nt < 4; ++nt) {
        const int cb = nw * 32 + nt * 8 + tg * 2;
        float2 b = *(const float2*)(bias + cb);
        #pragma unroll
        for (int mm = 0; mm < 2; ++mm) {
            const int r0 = mw * 32 + mm * 16 + qd;
            A[cb * ASTR + r0]           += acc[mm][nt][0] + b.x;
            A[(cb + 1) * ASTR + r0]     += acc[mm][nt][1] + b.y;
            A[cb * ASTR + r0 + 8]       += acc[mm][nt][2] + b.x;
            A[(cb + 1) * ASTR + r0 + 8] += acc[mm][nt][3] + b.y;
        }
    }
}

// LayerNorm: A col-major fp32 -> X row-major fp16. 4 threads/token.
__device__ __forceinline__ void lnA(const float* __restrict__ A, unsigned* __restrict__ X,
                                    const float* __restrict__ g, const float* __restrict__ be, int tid)
{
    const int t = tid >> 2, q = tid & 3;
    const float* Ac = A + q * 32 * ASTR + t;
    float v[32];
    float s = 0.f, sq = 0.f;
    #pragma unroll
    for (int i = 0; i < 32; ++i) {
        v[i] = Ac[i * ASTR];
        s += v[i]; sq += v[i] * v[i];
    }
    s  += __shfl_xor_sync(0xffffffffu, s, 1);
    sq += __shfl_xor_sync(0xffffffffu, sq, 1);
    s  += __shfl_xor_sync(0xffffffffu, s, 2);
    sq += __shfl_xor_sync(0xffffffffu, sq, 2);
    float m = s * (1.f / CC);
    float rs = rsqrtf(sq * (1.f / CC) - m * m + 1e-5f);

    const float2* g2 = (const float2*)(g + q * 32);
    const float2* b2 = (const float2*)(be + q * 32);
    unsigned* o = X + t * STRA + q * 16;
    #pragma unroll
    for (int i = 0; i < 16; ++i) {
        float2 gg = g2[i], bb = b2[i];
        o[i] = pk((v[2 * i] - m) * rs * gg.x + bb.x,
                  (v[2 * i + 1] - m) * rs * gg.y + bb.y);
    }
}

#define ZACC(a) { _Pragma("unroll") for (int _m = 0; _m < 2; ++_m) _Pragma("unroll") for (int _n = 0; _n < 4; ++_n) { a[_m][_n][0]=0.f; a[_m][_n][1]=0.f; a[_m][_n][2]=0.f; a[_m][_n][3]=0.f; } }

__global__ void __launch_bounds__(NTHREADS, 2)
polar_attention_kernel(
    const float* __restrict__ x,   const float* __restrict__ polar,
    const float* __restrict__ bq,  const float* __restrict__ bk,
    const float* __restrict__ bv,  const float* __restrict__ Wp,
    const float* __restrict__ bpv, const float* __restrict__ bo,
    const float* __restrict__ g1,  const float* __restrict__ be1,
    const float* __restrict__ g2,  const float* __restrict__ be2,
    const float* __restrict__ bf1, const float* __restrict__ bf2,
    float* __restrict__ out)
{
    extern __shared__ float sm[];
    unsigned* smu = (unsigned*)sm;
    float*    A   = sm + OFF_A;
    unsigned* X16 = smu + OFF_X;
    unsigned* Q16 = smu + OFF_Q;
    unsigned* K16 = smu + OFF_K;
    unsigned* V16 = smu + OFF_V;
    float*    pol = sm + OFF_POL;

    const int tid = threadIdx.x;
    const int n0  = blockIdx.x * TOK;
    const int b   = n0 / SS;
    const int s0  = n0 % SS;

    const float* xg = x + (size_t)(b * CC) * SS + s0;
    const float* pg = polar + (size_t)(b * PCH) * SS + s0;

    // ---- load x tile (col-major A) + polar ----
    #pragma unroll
    for (int idx = tid; idx < 2048; idx += NTHREADS) {
        int c = idx >> 4, t4 = (idx & 15) * 4;
        *(float4*)(A + c * ASTR + t4) = *(const float4*)(xg + (size_t)c * SS + t4);
    }
    for (int i = tid; i < 96; i += NTHREADS) {
        int p = i >> 4, t4 = (i & 15) * 4;
        *(float4*)(pol + p * 64 + t4) = *(const float4*)(pg + (size_t)p * SS + t4);
    }
    __syncthreads();

    // ---- x_with_polar = x + polar @ Wp + bp (A in place) ----
    #pragma unroll
    for (int idx = tid; idx < 2048; idx += NTHREADS) {
        int c = idx >> 4, t4 = (idx & 15) * 4;
        float4 v = *(const float4*)(A + c * ASTR + t4);
        #pragma unroll
        for (int p = 0; p < PCH; ++p) {
            float w = Wp[p * 128 + c];
            float4 pv = *(const float4*)(pol + p * 64 + t4);
            v.x = fmaf(pv.x, w, v.x); v.y = fmaf(pv.y, w, v.y);
            v.z = fmaf(pv.z, w, v.z); v.w = fmaf(pv.w, w, v.w);
        }
        float bb = bpv[c];
        v.x += bb; v.y += bb; v.z += bb; v.w += bb;
        *(float4*)(A + c * ASTR + t4) = v;
    }
    __syncthreads();

    // ---- LN1 -> X16 ----
    lnA(A, X16, g1, be1, tid);
    __syncthreads();

    // ---- Q,K,V (no syncs needed between: same input, disjoint outputs) ----
    float acc[2][4][4];
    ZACC(acc); gemm_f(g_wfrag,          X16, acc, tid); epi16(acc, Q16, bq, false, tid);
    ZACC(acc); gemm_f(g_wfrag + 8192,   X16, acc, tid); epi16(acc, K16, bk, false, tid);
    ZACC(acc); gemm_f(g_wfrag + 16384,  X16, acc, tid); epi16(acc, V16, bv, false, tid);
    __syncthreads();

    // ---- per-token cross-head attention: 4 thr/token, 2 heads each -> X16 ----
    {
        const int t = tid >> 2;
        const int h0q = (tid & 3) * 2;
        const unsigned* Qr = Q16 + t * STRA;
        const unsigned* Kr = K16 + t * STRA;
        const unsigned* Vr = V16 + t * STRA;
        #pragma unroll
        for (int hh = 0; hh < 2; ++hh) {
            const int h = h0q + hh;
            float q[16];
            #pragma unroll
            for (int i = 0; i < 8; ++i) {
                float2 f = up(Qr[h * 8 + i]);
                q[2 * i] = f.x; q[2 * i + 1] = f.y;
            }
            float sc[NHEAD];
            #pragma unroll
            for (int g = 0; g < NHEAD; ++g) {
                float s = 0.f;
                #pragma unroll
                for (int i = 0; i < 8; ++i) {
                    float2 f = up(Kr[g * 8 + i]);
                    s = fmaf(q[2 * i], f.x, s);
                    s = fmaf(q[2 * i + 1], f.y, s);
                }
                sc[g] = s * 0.25f;
            }
            float mx = sc[0];
            #pragma unroll
            for (int g = 1; g < NHEAD; ++g) mx = fmaxf(mx, sc[g]);
            float sum = 0.f;
            #pragma unroll
            for (int g = 0; g < NHEAD; ++g) { float e = __expf(sc[g] - mx); sc[g] = e; sum += e; }
            float inv = 1.f / sum;
            #pragma unroll
            for (int g = 0; g < NHEAD; ++g) sc[g] *= inv;

            float att[16];
            #pragma unroll
            for (int i = 0; i < 16; ++i) att[i] = 0.f;
            #pragma unroll
            for (int g = 0; g < NHEAD; ++g) {
                float w = sc[g];
                #pragma unroll
                for (int i = 0; i < 8; ++i) {
                    float2 f = up(Vr[g * 8 + i]);
                    att[2 * i]     = fmaf(w, f.x, att[2 * i]);
                    att[2 * i + 1] = fmaf(w, f.y, att[2 * i + 1]);
                }
            }
            #pragma unroll
            for (int i = 0; i < 8; ++i)
                X16[t * STRA + h * 8 + i] = pk(att[2 * i], att[2 * i + 1]);
        }
    }
    __syncthreads();

    // ---- out1 = attended @ Wo + bo + residual1 (A in place) ----
    ZACC(acc); gemm_f(g_wfrag + 24576, X16, acc, tid); epi32A(acc, A, bo, tid);
    __syncthreads();

    // ---- LN2 -> X16 ----
    lnA(A, X16, g2, be2, tid);
    __syncthreads();

    // ---- FFN: out2 = relu(xn2 @ W1 + bf1) @ W2 + bf2 + out1 ----
    float acc2[2][4][4];
    ZACC(acc2);
    #pragma unroll 1
    for (int jb = 0; jb < 4; ++jb) {
        float h1[2][4][4];
        ZACC(h1);
        gemm_f(g_wfrag + (4 + jb) * 8192, X16, h1, tid);
        epi16(h1, V16, bf1 + jb * 128, true, tid);
        __syncthreads();
        gemm_f(g_wfrag + (8 + jb) * 8192, V16, acc2, tid);
        __syncthreads();
    }
    epi32A(acc2, A, bf2, tid);
    __syncthreads();

    // ---- coalesced global store ----
    float* og = out + (size_t)(b * CC) * SS + s0;
    #pragma unroll
    for (int idx = tid; idx < 2048; idx += NTHREADS) {
        int c = idx >> 4, t4 = (idx & 15) * 4;
        *(float4*)(og + (size_t)c * SS + t4) = *(const float4*)(A + c * ASTR + t4);
    }
}

extern "C" void kernel_launch(void* const* d_in, const int* in_sizes, int n_in,
                              void* d_out, int out_size)
{
    (void)in_sizes; (void)n_in; (void)out_size;
    cudaFuncSetAttribute(polar_attention_kernel,
                         cudaFuncAttributeMaxDynamicSharedMemorySize, SMEM_BYTES);

    const float* x     = (const float*)d_in[0];
    const float* polar = (const float*)d_in[1];
    const float* Wq    = (const float*)d_in[2];
    const float* bq    = (const float*)d_in[3];
    const float* Wk    = (const float*)d_in[4];
    const float* bk    = (const float*)d_in[5];
    const float* Wv    = (const float*)d_in[6];
    const float* bv    = (const float*)d_in[7];
    const float* Wp    = (const float*)d_in[8];
    const float* bp    = (const float*)d_in[9];
    const float* Wo    = (const float*)d_in[10];
    const float* bo    = (const float*)d_in[11];
    const float* g1    = (const float*)d_in[12];
    const float* be1   = (const float*)d_in[13];
    const float* g2    = (const float*)d_in[14];
    const float* be2   = (const float*)d_in[15];
    const float* W1    = (const float*)d_in[16];
    const float* bf1   = (const float*)d_in[17];
    const float* W2    = (const float*)d_in[18];
    const float* bf2   = (const float*)d_in[19];
    float* out = (float*)d_out;

    convert_weights<<<384, NTHREADS>>>(Wq, Wk, Wv, Wo, W1, W2);

    dim3 grid(NTOK / TOK);
    polar_attention_kernel<<<grid, NTHREADS, SMEM_BYTES>>>(
        x, polar, bq, bk, bv, Wp, bp, bo, g1, be1, g2, be2, bf1, bf2, out);
}

// round 7
// speedup vs baseline: 9.4586x; 1.0947x over previous
#include <cuda_runtime.h>
#include <cuda_fp16.h>

#define CC   128
#define PCH  6
#define SS   131072
#define NTOK 262144
#define TOK  64
#define NTHREADS 256
#define NHEAD 8

#define STRA 68      // fp16 activation row stride (u32 words)
#define ASTR 68      // fp32 residual A column stride: A[c][t]

// ---- shared memory layout (32-bit word offsets) ----
#define OFF_A    0                       // fp32 A [128][68] col-major
#define OFF_X    (128*ASTR)
#define OFF_Q    (OFF_X + 64*STRA)
#define OFF_K    (OFF_Q + 64*STRA)
#define OFF_V    (OFF_K + 64*STRA)
#define OFF_POL  (OFF_V + 64*STRA)
#define SMEM_WORDS (OFF_POL + PCH*64)
#define SMEM_BYTES (SMEM_WORDS*4)        // 105984 B -> 2 CTAs/SM

// 12 fragment blocks of 128x128: Wq,Wk,Wv,Wo, W1 n-chunks x4, W2 k-chunks x4
__device__ unsigned g_wfrag[12 * 8192];

// ---- fp16 helpers ----
__device__ __forceinline__ unsigned pk(float lo, float hi) {
    __half2 h = __floats2half2_rn(lo, hi);
    return *reinterpret_cast<unsigned*>(&h);
}
__device__ __forceinline__ float2 up(unsigned w) {
    __half2 h = *reinterpret_cast<__half2*>(&w);
    return __half22float2(h);
}
__device__ __forceinline__ void mma16(float (&d)[4],
    unsigned a0, unsigned a1, unsigned a2, unsigned a3, unsigned b0, unsigned b1)
{
    asm("mma.sync.aligned.m16n8k16.row.col.f32.f16.f16.f32 "
        "{%0,%1,%2,%3}, {%4,%5,%6,%7}, {%8,%9}, {%0,%1,%2,%3};"
        : "+f"(d[0]), "+f"(d[1]), "+f"(d[2]), "+f"(d[3])
        : "r"(a0), "r"(a1), "r"(a2), "r"(a3), "r"(b0), "r"(b1));
}
__device__ __forceinline__ void ldsm4(unsigned (&a)[4], unsigned addr) {
    asm volatile("ldmatrix.sync.aligned.m8n8.x4.shared.b16 {%0,%1,%2,%3}, [%4];"
        : "=r"(a[0]), "=r"(a[1]), "=r"(a[2]), "=r"(a[3]) : "r"(addr));
}

// ---- weight conversion kernel: fp32 row-major -> fp16 fragment-major ----
__global__ void convert_weights(const float* __restrict__ Wq, const float* __restrict__ Wk,
                                const float* __restrict__ Wv, const float* __restrict__ Wo,
                                const float* __restrict__ W1, const float* __restrict__ W2)
{
    int gid = blockIdx.x * blockDim.x + threadIdx.x;
    int blk = gid >> 13;
    int w   = gid & 8191;
    int q4   = w & 3;
    int lane = (w >> 2) & 31;
    int h    = (w >> 7) & 1;
    int nw   = (w >> 8) & 3;
    int ks   = w >> 10;
    int j    = q4 & 1;
    int nt   = h * 2 + (q4 >> 1);
    int qd = lane >> 2, tg = lane & 3;
    int k = ks * 16 + tg * 2 + j * 8;
    int n = nw * 32 + nt * 8 + qd;

    const float* W; int ld = 128, k0 = 0, n0 = 0;
    if      (blk == 0) W = Wq;
    else if (blk == 1) W = Wk;
    else if (blk == 2) W = Wv;
    else if (blk == 3) W = Wo;
    else if (blk < 8)  { W = W1; ld = 512; n0 = (blk - 4) * 128; }
    else               { W = W2; k0 = (blk - 8) * 128; }

    const float* p = W + (size_t)(k0 + k) * ld + n0 + n;
    g_wfrag[gid] = pk(p[0], p[ld]);
}

// ---- GEMM: acc[2][4][4] += X[64x128 fp16] @ Wfrag, software pipelined ----
// warps: mw = wid&1 (32 rows), nw = wid>>1 (32 cols)
__device__ __forceinline__ void gemm_f(
    const unsigned* __restrict__ Wf,
    const unsigned* __restrict__ Xs,
    float (&acc)[2][4][4], int tid)
{
    const int lane = tid & 31, wid = tid >> 5;
    const int mw = wid & 1, nw = wid >> 1;

    // LDSM lane address: rows mw*32 + mm*16 + (lane&15); +16B for lanes 16..31
    unsigned abase;
    {
        const unsigned* p = Xs + (mw * 32 + (lane & 15)) * STRA;
        abase = (unsigned)__cvta_generic_to_shared(p) + ((lane >> 4) << 4);
    }
    const uint4* bp = (const uint4*)Wf + nw * 64 + lane;

    unsigned aC[2][4], aN[2][4];
    uint4 b0C, b1C, b0N, b1N;
    ldsm4(aC[0], abase);
    ldsm4(aC[1], abase + 16 * STRA * 4);
    b0C = bp[0]; b1C = bp[32];

    #pragma unroll
    for (int ks = 0; ks < 8; ++ks) {
        if (ks < 7) {
            unsigned an = abase + (ks + 1) * 32;
            ldsm4(aN[0], an);
            ldsm4(aN[1], an + 16 * STRA * 4);
            b0N = bp[(ks + 1) * 256];
            b1N = bp[(ks + 1) * 256 + 32];
        }
        #pragma unroll
        for (int mm = 0; mm < 2; ++mm) {
            mma16(acc[mm][0], aC[mm][0], aC[mm][1], aC[mm][2], aC[mm][3], b0C.x, b0C.y);
            mma16(acc[mm][1], aC[mm][0], aC[mm][1], aC[mm][2], aC[mm][3], b0C.z, b0C.w);
            mma16(acc[mm][2], aC[mm][0], aC[mm][1], aC[mm][2], aC[mm][3], b1C.x, b1C.y);
            mma16(acc[mm][3], aC[mm][0], aC[mm][1], aC[mm][2], aC[mm][3], b1C.z, b1C.w);
        }
        #pragma unroll
        for (int mm = 0; mm < 2; ++mm)
            #pragma unroll
            for (int r = 0; r < 4; ++r) aC[mm][r] = aN[mm][r];
        b0C = b0N; b1C = b1N;
    }
}

// epilogue -> fp16 activation buffer (+bias from gmem, optional relu)
__device__ __forceinline__ void epi16(float (&acc)[2][4][4], unsigned* __restrict__ dst,
                                      const float* __restrict__ bias, bool relu, int tid)
{
    const int lane = tid & 31, wid = tid >> 5;
    const int mw = wid & 1, nw = wid >> 1;
    const int qd = lane >> 2, tg = lane & 3;
    #pragma unroll
    for (int nt = 0; nt < 4; ++nt) {
        const int cb = nw * 32 + nt * 8 + tg * 2;
        float2 b = *(const float2*)(bias + cb);
        #pragma unroll
        for (int mm = 0; mm < 2; ++mm) {
            const int r0 = mw * 32 + mm * 16 + qd;
            float v0 = acc[mm][nt][0] + b.x, v1 = acc[mm][nt][1] + b.y;
            float v2 = acc[mm][nt][2] + b.x, v3 = acc[mm][nt][3] + b.y;
            if (relu) {
                v0 = fmaxf(v0, 0.f); v1 = fmaxf(v1, 0.f);
                v2 = fmaxf(v2, 0.f); v3 = fmaxf(v3, 0.f);
            }
            dst[r0 * STRA + (cb >> 1)]       = pk(v0, v1);
            dst[(r0 + 8) * STRA + (cb >> 1)] = pk(v2, v3);
        }
    }
}

// epilogue -> fp32 A (col-major) in place: A[c][t] += acc + bias
__device__ __forceinline__ void epi32A(float (&acc)[2][4][4], float* __restrict__ A,
                                       const float* __restrict__ bias, int tid)
{
    const int lane = tid & 31, wid = tid >> 5;
    const int mw = wid & 1, nw = wid >> 1;
    const int qd = lane >> 2, tg = lane & 3;
    #pragma unroll
    for (int nt = 0; nt < 4; ++nt) {
        const int cb = nw * 32 + nt * 8 + tg * 2;
        float2 b = *(const float2*)(bias + cb);
        #pragma unroll
        for (int mm = 0; mm < 2; ++mm) {
            const int r0 = mw * 32 + mm * 16 + qd;
            A[cb * ASTR + r0]           += acc[mm][nt][0] + b.x;
            A[(cb + 1) * ASTR + r0]     += acc[mm][nt][1] + b.y;
            A[cb * ASTR + r0 + 8]       += acc[mm][nt][2] + b.x;
            A[(cb + 1) * ASTR + r0 + 8] += acc[mm][nt][3] + b.y;
        }
    }
}

// LayerNorm: A col-major fp32 -> X row-major fp16. 4 threads/token.
__device__ __forceinline__ void lnA(const float* __restrict__ A, unsigned* __restrict__ X,
                                    const float* __restrict__ g, const float* __restrict__ be, int tid)
{
    const int t = tid >> 2, q = tid & 3;
    const float* Ac = A + q * 32 * ASTR + t;
    float v[32];
    float s = 0.f, sq = 0.f;
    #pragma unroll
    for (int i = 0; i < 32; ++i) {
        v[i] = Ac[i * ASTR];
        s += v[i]; sq += v[i] * v[i];
    }
    s  += __shfl_xor_sync(0xffffffffu, s, 1);
    sq += __shfl_xor_sync(0xffffffffu, sq, 1);
    s  += __shfl_xor_sync(0xffffffffu, s, 2);
    sq += __shfl_xor_sync(0xffffffffu, sq, 2);
    float m = s * (1.f / CC);
    float rs = rsqrtf(sq * (1.f / CC) - m * m + 1e-5f);

    const float2* g2 = (const float2*)(g + q * 32);
    const float2* b2 = (const float2*)(be + q * 32);
    unsigned* o = X + t * STRA + q * 16;
    #pragma unroll
    for (int i = 0; i < 16; ++i) {
        float2 gg = g2[i], bb = b2[i];
        o[i] = pk((v[2 * i] - m) * rs * gg.x + bb.x,
                  (v[2 * i + 1] - m) * rs * gg.y + bb.y);
    }
}

#define ZACC(a) { _Pragma("unroll") for (int _m = 0; _m < 2; ++_m) _Pragma("unroll") for (int _n = 0; _n < 4; ++_n) { a[_m][_n][0]=0.f; a[_m][_n][1]=0.f; a[_m][_n][2]=0.f; a[_m][_n][3]=0.f; } }

__global__ void __launch_bounds__(NTHREADS, 2)
polar_attention_kernel(
    const float* __restrict__ x,   const float* __restrict__ polar,
    const float* __restrict__ bq,  const float* __restrict__ bk,
    const float* __restrict__ bv,  const float* __restrict__ Wp,
    const float* __restrict__ bpv, const float* __restrict__ bo,
    const float* __restrict__ g1,  const float* __restrict__ be1,
    const float* __restrict__ g2,  const float* __restrict__ be2,
    const float* __restrict__ bf1, const float* __restrict__ bf2,
    float* __restrict__ out)
{
    extern __shared__ float sm[];
    unsigned* smu = (unsigned*)sm;
    float*    A   = sm + OFF_A;
    unsigned* X16 = smu + OFF_X;
    unsigned* Q16 = smu + OFF_Q;
    unsigned* K16 = smu + OFF_K;
    unsigned* V16 = smu + OFF_V;
    float*    pol = sm + OFF_POL;

    const int tid = threadIdx.x;
    const int n0  = blockIdx.x * TOK;
    const int b   = n0 / SS;
    const int s0  = n0 % SS;

    const float* xg = x + (size_t)(b * CC) * SS + s0;
    const float* pg = polar + (size_t)(b * PCH) * SS + s0;

    // ---- load x tile (col-major A) + polar ----
    #pragma unroll
    for (int idx = tid; idx < 2048; idx += NTHREADS) {
        int c = idx >> 4, t4 = (idx & 15) * 4;
        *(float4*)(A + c * ASTR + t4) = *(const float4*)(xg + (size_t)c * SS + t4);
    }
    for (int i = tid; i < 96; i += NTHREADS) {
        int p = i >> 4, t4 = (i & 15) * 4;
        *(float4*)(pol + p * 64 + t4) = *(const float4*)(pg + (size_t)p * SS + t4);
    }
    __syncthreads();

    // ---- x_with_polar = x + polar @ Wp + bp (A in place) ----
    #pragma unroll
    for (int idx = tid; idx < 2048; idx += NTHREADS) {
        int c = idx >> 4, t4 = (idx & 15) * 4;
        float4 v = *(const float4*)(A + c * ASTR + t4);
        #pragma unroll
        for (int p = 0; p < PCH; ++p) {
            float w = Wp[p * 128 + c];
            float4 pv = *(const float4*)(pol + p * 64 + t4);
            v.x = fmaf(pv.x, w, v.x); v.y = fmaf(pv.y, w, v.y);
            v.z = fmaf(pv.z, w, v.z); v.w = fmaf(pv.w, w, v.w);
        }
        float bb = bpv[c];
        v.x += bb; v.y += bb; v.z += bb; v.w += bb;
        *(float4*)(A + c * ASTR + t4) = v;
    }
    __syncthreads();

    // ---- LN1 -> X16 ----
    lnA(A, X16, g1, be1, tid);
    __syncthreads();

    // ---- Q,K,V ----
    float acc[2][4][4];
    ZACC(acc); gemm_f(g_wfrag,          X16, acc, tid); epi16(acc, Q16, bq, false, tid);
    ZACC(acc); gemm_f(g_wfrag + 8192,   X16, acc, tid); epi16(acc, K16, bk, false, tid);
    ZACC(acc); gemm_f(g_wfrag + 16384,  X16, acc, tid); epi16(acc, V16, bv, false, tid);
    __syncthreads();

    // ---- per-token cross-head attention: 4 thr/token, 2 heads each -> X16 ----
    {
        const int t = tid >> 2;
        const int h0q = (tid & 3) * 2;
        const unsigned* Qr = Q16 + t * STRA;
        const unsigned* Kr = K16 + t * STRA;
        const unsigned* Vr = V16 + t * STRA;
        #pragma unroll
        for (int hh = 0; hh < 2; ++hh) {
            const int h = h0q + hh;
            float q[16];
            #pragma unroll
            for (int i = 0; i < 8; ++i) {
                float2 f = up(Qr[h * 8 + i]);
                q[2 * i] = f.x; q[2 * i + 1] = f.y;
            }
            float sc[NHEAD];
            #pragma unroll
            for (int g = 0; g < NHEAD; ++g) {
                float s = 0.f;
                #pragma unroll
                for (int i = 0; i < 8; ++i) {
                    float2 f = up(Kr[g * 8 + i]);
                    s = fmaf(q[2 * i], f.x, s);
                    s = fmaf(q[2 * i + 1], f.y, s);
                }
                sc[g] = s * 0.25f;
            }
            float mx = sc[0];
            #pragma unroll
            for (int g = 1; g < NHEAD; ++g) mx = fmaxf(mx, sc[g]);
            float sum = 0.f;
            #pragma unroll
            for (int g = 0; g < NHEAD; ++g) { float e = __expf(sc[g] - mx); sc[g] = e; sum += e; }
            float inv = 1.f / sum;
            #pragma unroll
            for (int g = 0; g < NHEAD; ++g) sc[g] *= inv;

            float att[16];
            #pragma unroll
            for (int i = 0; i < 16; ++i) att[i] = 0.f;
            #pragma unroll
            for (int g = 0; g < NHEAD; ++g) {
                float w = sc[g];
                #pragma unroll
                for (int i = 0; i < 8; ++i) {
                    float2 f = up(Vr[g * 8 + i]);
                    att[2 * i]     = fmaf(w, f.x, att[2 * i]);
                    att[2 * i + 1] = fmaf(w, f.y, att[2 * i + 1]);
                }
            }
            #pragma unroll
            for (int i = 0; i < 8; ++i)
                X16[t * STRA + h * 8 + i] = pk(att[2 * i], att[2 * i + 1]);
        }
    }
    __syncthreads();

    // ---- out1 = attended @ Wo + bo + residual1 (A in place) ----
    ZACC(acc); gemm_f(g_wfrag + 24576, X16, acc, tid); epi32A(acc, A, bo, tid);
    __syncthreads();

    // ---- LN2 -> X16 ----
    lnA(A, X16, g2, be2, tid);
    __syncthreads();

    // ---- FFN ----
    float acc2[2][4][4];
    ZACC(acc2);
    #pragma unroll 1
    for (int jb = 0; jb < 4; ++jb) {
        float h1[2][4][4];
        ZACC(h1);
        gemm_f(g_wfrag + (4 + jb) * 8192, X16, h1, tid);
        epi16(h1, V16, bf1 + jb * 128, true, tid);
        __syncthreads();
        gemm_f(g_wfrag + (8 + jb) * 8192, V16, acc2, tid);
        __syncthreads();
    }
    epi32A(acc2, A, bf2, tid);
    __syncthreads();

    // ---- coalesced global store ----
    float* og = out + (size_t)(b * CC) * SS + s0;
    #pragma unroll
    for (int idx = tid; idx < 2048; idx += NTHREADS) {
        int c = idx >> 4, t4 = (idx & 15) * 4;
        *(float4*)(og + (size_t)c * SS + t4) = *(const float4*)(A + c * ASTR + t4);
    }
}

extern "C" void kernel_launch(void* const* d_in, const int* in_sizes, int n_in,
                              void* d_out, int out_size)
{
    (void)in_sizes; (void)n_in; (void)out_size;
    cudaFuncSetAttribute(polar_attention_kernel,
                         cudaFuncAttributeMaxDynamicSharedMemorySize, SMEM_BYTES);

    const float* x     = (const float*)d_in[0];
    const float* polar = (const float*)d_in[1];
    const float* Wq    = (const float*)d_in[2];
    const float* bq    = (const float*)d_in[3];
    const float* Wk    = (const float*)d_in[4];
    const float* bk    = (const float*)d_in[5];
    const float* Wv    = (const float*)d_in[6];
    const float* bv    = (const float*)d_in[7];
    const float* Wp    = (const float*)d_in[8];
    const float* bp    = (const float*)d_in[9];
    const float* Wo    = (const float*)d_in[10];
    const float* bo    = (const float*)d_in[11];
    const float* g1    = (const float*)d_in[12];
    const float* be1   = (const float*)d_in[13];
    const float* g2    = (const float*)d_in[14];
    const float* be2   = (const float*)d_in[15];
    const float* W1    = (const float*)d_in[16];
    const float* bf1   = (const float*)d_in[17];
    const float* W2    = (const float*)d_in[18];
    const float* bf2   = (const float*)d_in[19];
    float* out = (float*)d_out;

    convert_weights<<<384, NTHREADS>>>(Wq, Wk, Wv, Wo, W1, W2);

    dim3 grid(NTOK / TOK);
    polar_attention_kernel<<<grid, NTHREADS, SMEM_BYTES>>>(
        x, polar, bq, bk, bv, Wp, bp, bo, g1, be1, g2, be2, bf1, bf2, out);
}